// round 11
// baseline (speedup 1.0000x reference)
#include <cuda_runtime.h>
#include <cuda_fp16.h>
#include <cstdint>
#include <math.h>

#define LNUM  12
#define C     1024
#define HN    16
#define HD    64
#define FF    4096
#define SEQ   256
#define BATCH 16
#define CBOOK 1024
#define NTOK  257
#define TOK   (BATCH*NTOK)   // 4112
#define EPS   1e-6f

typedef __half fp16;
struct __align__(8) H4 { __half2 a, b; };

// ---------------- scratch (device globals) -----------------------------------
__device__ float g_x[TOK*C];             // residual stream fp32
__device__ fp16  g_h[TOK*C];             // ln output (GEMM A)
__device__ float g_qkv[TOK*3*C];         // qkv fp32 (un-normalized; attn norms in-kernel)
__device__ fp16  g_o[TOK*C];             // attn out (GEMM A)
__device__ fp16  g_ff[TOK*FF];           // gelu out (GEMM A)
__device__ fp16  g_cact[BATCH*C];        // silu(c) (GEMM A)
__device__ float g_mod[LNUM*BATCH*6*C];  // per-layer modulation
__device__ float g_fm[BATCH*2*C];

// fp16 copies of all weights (converted every launch; deterministic)
__device__ fp16 w_qkv [LNUM*C*3*C];
__device__ fp16 w_proj[LNUM*C*C];
__device__ fp16 w_fc1 [LNUM*C*FF];
__device__ fp16 w_fc2 [LNUM*FF*C];
__device__ fp16 w_ada [LNUM*C*6*C];
__device__ fp16 w_fin [C*2*C];
__device__ fp16 w_head[C*CBOOK];

// ---------------- helpers ---------------------------------------------------
__device__ __forceinline__ float gelu_tanh(float x) {
    float x3 = x*x*x;
    float t  = tanhf(0.7978845608028654f*(x + 0.044715f*x3));
    return 0.5f*x*(1.0f + t);
}

__device__ __forceinline__ void cp_async16(uint32_t s, const void* g, bool p) {
    int sz = p ? 16 : 0;
    asm volatile("cp.async.cg.shared.global [%0], [%1], 16, %2;\n"
                 :: "r"(s), "l"(g), "r"(sz));
}
__device__ __forceinline__ void cp_commit() { asm volatile("cp.async.commit_group;\n"); }

__device__ __forceinline__ void ldm_x4(uint32_t &r0, uint32_t &r1, uint32_t &r2, uint32_t &r3, uint32_t a){
    asm volatile("ldmatrix.sync.aligned.m8n8.x4.shared.b16 {%0,%1,%2,%3},[%4];"
                 : "=r"(r0),"=r"(r1),"=r"(r2),"=r"(r3) : "r"(a));
}
__device__ __forceinline__ void ldm_x4_t(uint32_t &r0, uint32_t &r1, uint32_t &r2, uint32_t &r3, uint32_t a){
    asm volatile("ldmatrix.sync.aligned.m8n8.x4.trans.shared.b16 {%0,%1,%2,%3},[%4];"
                 : "=r"(r0),"=r"(r1),"=r"(r2),"=r"(r3) : "r"(a));
}
__device__ __forceinline__ void mma_fp16(float* c, const uint32_t* a, uint32_t b0, uint32_t b1){
    asm volatile("mma.sync.aligned.m16n8k16.row.col.f32.f16.f16.f32 "
                 "{%0,%1,%2,%3},{%4,%5,%6,%7},{%8,%9},{%0,%1,%2,%3};"
                 : "+f"(c[0]),"+f"(c[1]),"+f"(c[2]),"+f"(c[3])
                 : "r"(a[0]),"r"(a[1]),"r"(a[2]),"r"(a[3]),"r"(b0),"r"(b1));
}

// ---------------- fused fp32 -> fp16 conversion (one launch, 7 segments) ----
struct CvtDesc {
    const float* src[7];
    fp16*        dst[7];
    long long    off[8];
};
__global__ void cvt_all_kernel(CvtDesc d) {
    long long i = (long long)blockIdx.x*blockDim.x + threadIdx.x;
    if (i >= d.off[7]) return;
    int s = 0;
    #pragma unroll
    for (int k = 1; k < 7; k++) if (i >= d.off[k]) s = k;
    long long j = i - d.off[s];
    float4 v = ((const float4*)d.src[s])[j];
    H4 hv;
    hv.a = __floats2half2_rn(v.x, v.y);
    hv.b = __floats2half2_rn(v.z, v.w);
    ((H4*)d.dst[s])[j] = hv;
}

// ---------------- embedding + conditioning ----------------------------------
__global__ void embed_kernel(const int* __restrict__ ids, const int* __restrict__ cond,
                             const float* __restrict__ table, const float* __restrict__ pos,
                             float* __restrict__ x)
{
    int i = blockIdx.x*blockDim.x + threadIdx.x;
    if (i >= TOK*C) return;
    int r = i / C, c = i % C;
    int b = r / NTOK, n = r % NTOK;
    int id = (n == 0) ? (cond[b] + CBOOK + 1) : ids[b*SEQ + (n-1)];
    x[i] = table[(size_t)id*C + c] + pos[(size_t)n*C + c];
}

__global__ void cact_kernel(const int* __restrict__ cond, const float* __restrict__ table,
                            fp16* __restrict__ cact)
{
    int i = blockIdx.x*blockDim.x + threadIdx.x;
    if (i >= BATCH*C) return;
    int b = i / C, c = i % C;
    float v = table[(size_t)(cond[b] + CBOOK + 1)*C + c];
    cact[i] = __float2half(v / (1.0f + __expf(-v)));
}

// ---------------- LayerNorm + adaLN modulate (fp16 out, vectorized) ---------
__global__ void ln_mod_kernel(const float* __restrict__ x,
                              const float* __restrict__ s, const float* __restrict__ bb,
                              const float* __restrict__ mod, int shift_off, int scale_off,
                              int modStride, fp16* __restrict__ out)
{
    __shared__ float sh[16];
    int r = blockIdx.x;
    int t = threadIdx.x;
    const float4 xv = ((const float4*)(x + (size_t)r*C))[t];
    float sum = xv.x + xv.y + xv.z + xv.w;
    float sq  = xv.x*xv.x + xv.y*xv.y + xv.z*xv.z + xv.w*xv.w;
    int lane = t & 31, w = t >> 5;
    #pragma unroll
    for (int o = 16; o; o >>= 1) {
        sum += __shfl_xor_sync(0xffffffffu, sum, o);
        sq  += __shfl_xor_sync(0xffffffffu, sq,  o);
    }
    if (lane == 0) { sh[w] = sum; sh[8+w] = sq; }
    __syncthreads();
    if (t < 32) {
        float a  = (lane < 8) ? sh[lane]   : 0.f;
        float b2 = (lane < 8) ? sh[8+lane] : 0.f;
        #pragma unroll
        for (int o = 4; o; o >>= 1) {
            a  += __shfl_xor_sync(0xffffffffu, a,  o);
            b2 += __shfl_xor_sync(0xffffffffu, b2, o);
        }
        if (lane == 0) { sh[0] = a; sh[1] = b2; }
    }
    __syncthreads();
    float mu   = sh[0] * (1.0f/C);
    float var  = sh[1] * (1.0f/C) - mu*mu;
    float rstd = rsqrtf(var + EPS);
    int b = r / NTOK;
    const float* m = mod + (size_t)b*modStride;
    float4 msc = ((const float4*)(m + scale_off))[t];
    float4 msh = ((const float4*)(m + shift_off))[t];
    float y0 = (xv.x - mu)*rstd, y1 = (xv.y - mu)*rstd;
    float y2 = (xv.z - mu)*rstd, y3 = (xv.w - mu)*rstd;
    if (s) {
        float4 sv = ((const float4*)s)[t];
        float4 bv = ((const float4*)bb)[t];
        y0 = y0*sv.x + bv.x; y1 = y1*sv.y + bv.y;
        y2 = y2*sv.z + bv.z; y3 = y3*sv.w + bv.w;
    }
    y0 = y0*(1.0f + msc.x) + msh.x;
    y1 = y1*(1.0f + msc.y) + msh.y;
    y2 = y2*(1.0f + msc.z) + msh.z;
    y3 = y3*(1.0f + msc.w) + msh.w;
    H4 hv;
    hv.a = __floats2half2_rn(y0, y1);
    hv.b = __floats2half2_rn(y2, y3);
    ((H4*)(out + (size_t)r*C))[t] = hv;
}

// ---------------- causal attention + fused qk-norm (fp16 out) ----------------
#define KS2 68
#define ATTN_SMEM_FLOATS (2*NTOK*KS2 + 8*264 + 8*64)
__global__ void attn_kernel(const float* __restrict__ qkv,
                            const float* __restrict__ qns, const float* __restrict__ qnb,
                            const float* __restrict__ kns, const float* __restrict__ knb,
                            fp16* __restrict__ o)
{
    extern __shared__ float sm[];
    float* ksm = sm;                     // [NTOK][68]
    float* vsm = sm + NTOK*KS2;          // [NTOK][68]
    float* scb = vsm + NTOK*KS2;         // [8][264]
    float* qsm = scb + 8*264;            // [8][64]

    int bh = blockIdx.x;
    int b = bh / HN, h = bh % HN;
    int tid = threadIdx.x, lane = tid & 31, w = tid >> 5;

    // per-lane norm params (2 dims per lane)
    float qs0 = qns[lane], qs1 = qns[lane+32];
    float qb0 = qnb[lane], qb1 = qnb[lane+32];
    float ks0 = kns[lane], ks1 = kns[lane+32];
    float kb0 = knb[lane], kb1 = knb[lane+32];

    for (int i = tid; i < NTOK*HD; i += 256) {
        int n = i >> 6, d = i & 63;
        const float* row = qkv + (size_t)(b*NTOK + n)*3*C + h*HD;
        ksm[n*KS2 + d] = row[C   + d];
        vsm[n*KS2 + d] = row[2*C + d];
    }
    __syncthreads();

    // fused K layernorm: each warp normalizes rows w, w+8, ...
    for (int j = w; j < NTOK; j += 8) {
        float* kr = ksm + j*KS2;
        float v0 = kr[lane], v1 = kr[lane+32];
        float sum = v0 + v1;
        #pragma unroll
        for (int o2 = 16; o2; o2 >>= 1) sum += __shfl_xor_sync(0xffffffffu, sum, o2);
        float mu = sum * (1.0f/HD);
        float d0 = v0 - mu, d1 = v1 - mu;
        float sq = d0*d0 + d1*d1;
        #pragma unroll
        for (int o2 = 16; o2; o2 >>= 1) sq += __shfl_xor_sync(0xffffffffu, sq, o2);
        float rstd = rsqrtf(sq*(1.0f/HD) + EPS);
        kr[lane]    = d0*rstd*ks0 + kb0;
        kr[lane+32] = d1*rstd*ks1 + kb1;
    }
    __syncthreads();

    float* sc = scb + w*264;
    float* qb = qsm + w*64;
    for (int q = w; q < NTOK; q += 8) {
        const float* qrow = qkv + (size_t)(b*NTOK + q)*3*C + h*HD;
        // fused q layernorm
        float v0 = qrow[lane], v1 = qrow[lane+32];
        float sum = v0 + v1;
        #pragma unroll
        for (int o2 = 16; o2; o2 >>= 1) sum += __shfl_xor_sync(0xffffffffu, sum, o2);
        float mu = sum * (1.0f/HD);
        float d0 = v0 - mu, d1 = v1 - mu;
        float sq = d0*d0 + d1*d1;
        #pragma unroll
        for (int o2 = 16; o2; o2 >>= 1) sq += __shfl_xor_sync(0xffffffffu, sq, o2);
        float rstd = rsqrtf(sq*(1.0f/HD) + EPS);
        qb[lane]    = d0*rstd*qs0 + qb0;
        qb[lane+32] = d1*rstd*qs1 + qb1;
        __syncwarp();
        float4 q4[16];
        #pragma unroll
        for (int i = 0; i < 16; i++) q4[i] = ((const float4*)qb)[i];

        float mx = -1e30f;
        for (int j = lane; j <= q; j += 32) {
            const float4* kr = (const float4*)(ksm + j*KS2);
            float s = 0.f;
            #pragma unroll
            for (int i = 0; i < 16; i++) {
                float4 kv = kr[i];
                s += q4[i].x*kv.x + q4[i].y*kv.y + q4[i].z*kv.z + q4[i].w*kv.w;
            }
            s *= 0.125f;
            sc[j] = s;
            mx = fmaxf(mx, s);
        }
        #pragma unroll
        for (int off = 16; off; off >>= 1) mx = fmaxf(mx, __shfl_xor_sync(0xffffffffu, mx, off));
        __syncwarp();
        float Z = 0.f;
        for (int j = lane; j <= q; j += 32) {
            float p = __expf(sc[j] - mx);
            sc[j] = p; Z += p;
        }
        #pragma unroll
        for (int off = 16; off; off >>= 1) Z += __shfl_xor_sync(0xffffffffu, Z, off);
        __syncwarp();
        // PV: lane owns dims (2*lane, 2*lane+1)
        float o0 = 0.f, o1 = 0.f;
        const float* vbase = vsm + 2*lane;
        int j = 0;
        for (; j + 3 <= q; j += 4) {
            float p0 = sc[j], p1 = sc[j+1], p2 = sc[j+2], p3 = sc[j+3];
            float2 v0v = *(const float2*)(vbase + (j  )*KS2);
            float2 v1v = *(const float2*)(vbase + (j+1)*KS2);
            float2 v2v = *(const float2*)(vbase + (j+2)*KS2);
            float2 v3v = *(const float2*)(vbase + (j+3)*KS2);
            o0 += p0*v0v.x + p1*v1v.x + p2*v2v.x + p3*v3v.x;
            o1 += p0*v0v.y + p1*v1v.y + p2*v2v.y + p3*v3v.y;
        }
        for (; j <= q; j++) {
            float p = sc[j];
            float2 v0v = *(const float2*)(vbase + j*KS2);
            o0 += p*v0v.x;
            o1 += p*v0v.y;
        }
        float inv = 1.0f / Z;
        fp16* orow = o + (size_t)(b*NTOK + q)*C + h*HD;
        *(__half2*)(orow + 2*lane) = __floats2half2_rn(o0*inv, o1*inv);
        __syncwarp();
    }
}

// ---------------- fp16 tensor-core GEMM 128x128x32, 4-stage pipeline ---------
// epi 0: Cf = acc + bias ; epi 1: Cb = gelu(acc+bias) fp16 ; epi 2: Cf = res + gate*(acc+bias)
// Optional z-batching: B/bias/Cf advance by zB/zBias/zC per blockIdx.z.
#define BM 128
#define BN 128
#define BK 32
#define ASTR 40
#define BSTR 136
#define STAGES 4
#define A_STAGE (BM*ASTR)
#define B_STAGE (BK*BSTR)
#define GEMM_SMEM ((STAGES*A_STAGE + STAGES*B_STAGE)*2)

__global__ __launch_bounds__(256) void gemm_fp16_kernel(
    const fp16* __restrict__ A, const fp16* __restrict__ B,
    const float* __restrict__ bias, const float* __restrict__ res,
    const float* __restrict__ gate, int gateStride,
    float* __restrict__ Cf, fp16* __restrict__ Cb,
    int M, int N, int K, int epi, int rowsPerBatch,
    size_t zB, size_t zC, int zBias)
{
    extern __shared__ __align__(16) fp16 smemh[];
    fp16* As = smemh;
    fp16* Bs = smemh + STAGES*A_STAGE;

    B    += (size_t)blockIdx.z * zB;
    bias += (size_t)blockIdx.z * zBias;
    Cf   += (size_t)blockIdx.z * zC;

    int tid = threadIdx.x;
    int warp = tid >> 5, lane = tid & 31;
    int wm = warp >> 1, wn = warp & 1;
    int m0 = blockIdx.y*BM, n0 = blockIdx.x*BN;

    float acc[2][8][4];
    #pragma unroll
    for (int i = 0; i < 2; i++)
        #pragma unroll
        for (int j = 0; j < 8; j++)
            #pragma unroll
            for (int k = 0; k < 4; k++) acc[i][j][k] = 0.f;

    int ar0 = tid >> 2;
    int ach = (tid & 3) << 3;
    int br0 = tid >> 4;
    int bch = (tid & 15) << 3;
    bool av0 = (m0 + ar0)      < M;
    bool av1 = (m0 + ar0 + 64) < M;

    int KT = K/BK;

    // prologue: stages 0..STAGES-2
    #pragma unroll
    for (int s = 0; s < STAGES-1; s++) {
        int k0 = s*BK;
        if (s < KT) {
            cp_async16((uint32_t)__cvta_generic_to_shared(&As[s*A_STAGE + ar0*ASTR + ach]),
                       A + (size_t)(m0+ar0)*K + k0 + ach, av0);
            cp_async16((uint32_t)__cvta_generic_to_shared(&As[s*A_STAGE + (ar0+64)*ASTR + ach]),
                       A + (size_t)(m0+ar0+64)*K + k0 + ach, av1);
            cp_async16((uint32_t)__cvta_generic_to_shared(&Bs[s*B_STAGE + br0*BSTR + bch]),
                       B + (size_t)(k0+br0)*N + n0 + bch, true);
            cp_async16((uint32_t)__cvta_generic_to_shared(&Bs[s*B_STAGE + (br0+16)*BSTR + bch]),
                       B + (size_t)(k0+br0+16)*N + n0 + bch, true);
        }
        cp_commit();
    }

    for (int kt = 0; kt < KT; kt++) {
        asm volatile("cp.async.wait_group %0;\n" :: "n"(STAGES-2));
        __syncthreads();

        int nk = kt + STAGES - 1;
        if (nk < KT) {
            int sl = nk % STAGES;
            int k0 = nk*BK;
            cp_async16((uint32_t)__cvta_generic_to_shared(&As[sl*A_STAGE + ar0*ASTR + ach]),
                       A + (size_t)(m0+ar0)*K + k0 + ach, av0);
            cp_async16((uint32_t)__cvta_generic_to_shared(&As[sl*A_STAGE + (ar0+64)*ASTR + ach]),
                       A + (size_t)(m0+ar0+64)*K + k0 + ach, av1);
            cp_async16((uint32_t)__cvta_generic_to_shared(&Bs[sl*B_STAGE + br0*BSTR + bch]),
                       B + (size_t)(k0+br0)*N + n0 + bch, true);
            cp_async16((uint32_t)__cvta_generic_to_shared(&Bs[sl*B_STAGE + (br0+16)*BSTR + bch]),
                       B + (size_t)(k0+br0+16)*N + n0 + bch, true);
        }
        cp_commit();

        const fp16* Ab = As + (kt % STAGES)*A_STAGE;
        const fp16* Bb = Bs + (kt % STAGES)*B_STAGE;
        #pragma unroll
        for (int ks = 0; ks < 2; ks++) {
            uint32_t a[2][4];
            #pragma unroll
            for (int mi = 0; mi < 2; mi++) {
                int row  = wm*32 + mi*16 + (lane & 15);
                int koff = ks*16 + ((lane >> 4) << 3);
                ldm_x4(a[mi][0], a[mi][1], a[mi][2], a[mi][3],
                       (uint32_t)__cvta_generic_to_shared(&Ab[row*ASTR + koff]));
            }
            #pragma unroll
            for (int ntp = 0; ntp < 4; ntp++) {
                int kr   = ks*16 + (lane & 7) + (((lane >> 3) & 1) << 3);
                int noff = wn*64 + ntp*16 + (((lane >> 4) & 1) << 3);
                uint32_t b0, b1, b2, b3;
                ldm_x4_t(b0, b1, b2, b3,
                         (uint32_t)__cvta_generic_to_shared(&Bb[kr*BSTR + noff]));
                #pragma unroll
                for (int mi = 0; mi < 2; mi++) {
                    mma_fp16(acc[mi][2*ntp],   a[mi], b0, b1);
                    mma_fp16(acc[mi][2*ntp+1], a[mi], b2, b3);
                }
            }
        }
    }

    // epilogue
    int rbase = m0 + wm*32 + (lane >> 2);
    int cbase = n0 + wn*64 + (lane & 3)*2;
    #pragma unroll
    for (int mi = 0; mi < 2; mi++) {
        #pragma unroll
        for (int hh = 0; hh < 2; hh++) {
            int row = rbase + mi*16 + hh*8;
            if (row >= M) continue;
            int bidx = row / rowsPerBatch;
            #pragma unroll
            for (int nt = 0; nt < 8; nt++) {
                int col = cbase + nt*8;
                float v0 = acc[mi][nt][2*hh]   + bias[col];
                float v1 = acc[mi][nt][2*hh+1] + bias[col+1];
                if (epi == 1) {
                    v0 = gelu_tanh(v0); v1 = gelu_tanh(v1);
                    *(__half2*)(Cb + (size_t)row*N + col) = __floats2half2_rn(v0, v1);
                } else if (epi == 2) {
                    const float* rr = res + (size_t)row*N + col;
                    const float* gg = gate + (size_t)bidx*gateStride + col;
                    v0 = rr[0] + gg[0]*v0;
                    v1 = rr[1] + gg[1]*v1;
                    *(float2*)(Cf + (size_t)row*N + col) = make_float2(v0, v1);
                } else {
                    *(float2*)(Cf + (size_t)row*N + col) = make_float2(v0, v1);
                }
            }
        }
    }
}

// ---------------- driver -----------------------------------------------------
extern "C" void kernel_launch(void* const* d_in, const int* in_sizes, int n_in,
                              void* d_out, int out_size)
{
    const int*   ids   = (const int*)  d_in[0];
    const int*   cond  = (const int*)  d_in[1];
    const float* table = (const float*)d_in[2];
    const float* pos   = (const float*)d_in[3];
    const float* n1s   = (const float*)d_in[4];
    const float* n1b   = (const float*)d_in[5];
    const float* qkvw  = (const float*)d_in[6];
    const float* qkvb  = (const float*)d_in[7];
    const float* qns   = (const float*)d_in[8];
    const float* qnb   = (const float*)d_in[9];
    const float* kns   = (const float*)d_in[10];
    const float* knb   = (const float*)d_in[11];
    const float* projw = (const float*)d_in[12];
    const float* projb = (const float*)d_in[13];
    const float* n2s   = (const float*)d_in[14];
    const float* n2b   = (const float*)d_in[15];
    const float* f1w   = (const float*)d_in[16];
    const float* f1b   = (const float*)d_in[17];
    const float* f2w   = (const float*)d_in[18];
    const float* f2b   = (const float*)d_in[19];
    const float* aw    = (const float*)d_in[20];
    const float* ab    = (const float*)d_in[21];
    const float* fw    = (const float*)d_in[22];
    const float* fb    = (const float*)d_in[23];
    const float* hw    = (const float*)d_in[24];
    const float* hb    = (const float*)d_in[25];
    float* out = (float*)d_out;

    void *vx, *vh, *vqkv, *vo, *vff, *vcact, *vmod, *vfm;
    void *vwqkv, *vwproj, *vwfc1, *vwfc2, *vwada, *vwfin, *vwhead;
    cudaGetSymbolAddress(&vx,    g_x);
    cudaGetSymbolAddress(&vh,    g_h);
    cudaGetSymbolAddress(&vqkv,  g_qkv);
    cudaGetSymbolAddress(&vo,    g_o);
    cudaGetSymbolAddress(&vff,   g_ff);
    cudaGetSymbolAddress(&vcact, g_cact);
    cudaGetSymbolAddress(&vmod,  g_mod);
    cudaGetSymbolAddress(&vfm,   g_fm);
    cudaGetSymbolAddress(&vwqkv, w_qkv);
    cudaGetSymbolAddress(&vwproj,w_proj);
    cudaGetSymbolAddress(&vwfc1, w_fc1);
    cudaGetSymbolAddress(&vwfc2, w_fc2);
    cudaGetSymbolAddress(&vwada, w_ada);
    cudaGetSymbolAddress(&vwfin, w_fin);
    cudaGetSymbolAddress(&vwhead,w_head);

    float* px    = (float*)vx;
    fp16*  ph    = (fp16*) vh;
    float* pqkv  = (float*)vqkv;
    fp16*  po    = (fp16*) vo;
    fp16*  pff   = (fp16*) vff;
    fp16*  pcact = (fp16*) vcact;
    float* pmod  = (float*)vmod;
    float* pfm   = (float*)vfm;
    fp16*  bwqkv = (fp16*) vwqkv;
    fp16*  bwproj= (fp16*) vwproj;
    fp16*  bwfc1 = (fp16*) vwfc1;
    fp16*  bwfc2 = (fp16*) vwfc2;
    fp16*  bwada = (fp16*) vwada;
    fp16*  bwfin = (fp16*) vwfin;
    fp16*  bwhead= (fp16*) vwhead;

    int attnSmem = ATTN_SMEM_FLOATS * (int)sizeof(float);
    cudaFuncSetAttribute(attn_kernel, cudaFuncAttributeMaxDynamicSharedMemorySize, attnSmem);
    cudaFuncSetAttribute(gemm_fp16_kernel, cudaFuncAttributeMaxDynamicSharedMemorySize, GEMM_SMEM);

    // single fused conversion launch
    CvtDesc cd;
    long long c0 = (long long)LNUM*C*3*C/4;
    long long c1 = (long long)LNUM*C*C/4;
    long long c2 = (long long)LNUM*C*FF/4;
    long long c3 = (long long)LNUM*FF*C/4;
    long long c4 = (long long)LNUM*C*6*C/4;
    long long c5 = (long long)C*2*C/4;
    long long c6 = (long long)C*CBOOK/4;
    cd.src[0]=qkvw;  cd.dst[0]=bwqkv;
    cd.src[1]=projw; cd.dst[1]=bwproj;
    cd.src[2]=f1w;   cd.dst[2]=bwfc1;
    cd.src[3]=f2w;   cd.dst[3]=bwfc2;
    cd.src[4]=aw;    cd.dst[4]=bwada;
    cd.src[5]=fw;    cd.dst[5]=bwfin;
    cd.src[6]=hw;    cd.dst[6]=bwhead;
    cd.off[0]=0;
    cd.off[1]=c0;
    cd.off[2]=c0+c1;
    cd.off[3]=c0+c1+c2;
    cd.off[4]=c0+c1+c2+c3;
    cd.off[5]=c0+c1+c2+c3+c4;
    cd.off[6]=c0+c1+c2+c3+c4+c5;
    cd.off[7]=c0+c1+c2+c3+c4+c5+c6;
    cvt_all_kernel<<<(unsigned)((cd.off[7] + 255)/256), 256>>>(cd);

    embed_kernel<<<(TOK*C + 255)/256, 256>>>(ids, cond, table, pos, px);
    cact_kernel<<<(BATCH*C + 255)/256, 256>>>(cond, table, pcact);

    // all layers' adaLN modulation in one batched GEMM: mod[l] = silu(c) @ aw[l] + ab[l]
    gemm_fp16_kernel<<<dim3(6*C/BN, 1, LNUM), 256, GEMM_SMEM>>>(
        pcact, bwada, ab, nullptr, nullptr, 0, pmod, nullptr,
        BATCH, 6*C, C, 0, NTOK,
        (size_t)C*6*C, (size_t)BATCH*6*C, 6*C);

    const int MB = (TOK + BM - 1) / BM;   // 33

    for (int l = 0; l < LNUM; l++) {
        float* pmodL = pmod + (size_t)l*BATCH*6*C;
        // h = ln1(x)*(1+sc_msa)+sh_msa
        ln_mod_kernel<<<TOK, 256>>>(px, n1s + (size_t)l*C, n1b + (size_t)l*C,
                                    pmodL, 0, C, 6*C, ph);
        // qkv = h @ qkv_w + qkv_b
        gemm_fp16_kernel<<<dim3(3*C/BN, MB), 256, GEMM_SMEM>>>(
            ph, bwqkv + (size_t)l*C*3*C, qkvb + (size_t)l*3*C,
            nullptr, nullptr, 0, pqkv, nullptr, TOK, 3*C, C, 0, NTOK, 0, 0, 0);
        // causal attention (fused qk layernorm)
        attn_kernel<<<BATCH*HN, 256, attnSmem>>>(pqkv,
            qns + (size_t)l*HD, qnb + (size_t)l*HD,
            kns + (size_t)l*HD, knb + (size_t)l*HD, po);
        // x = x + g_msa * (o @ proj_w + proj_b)
        gemm_fp16_kernel<<<dim3(C/BN, MB), 256, GEMM_SMEM>>>(
            po, bwproj + (size_t)l*C*C, projb + (size_t)l*C,
            px, pmodL + 2*C, 6*C, px, nullptr, TOK, C, C, 2, NTOK, 0, 0, 0);
        // h = ln2(x)*(1+sc_mlp)+sh_mlp
        ln_mod_kernel<<<TOK, 256>>>(px, n2s + (size_t)l*C, n2b + (size_t)l*C,
                                    pmodL, 3*C, 4*C, 6*C, ph);
        // ff = gelu(h @ fc1_w + fc1_b)  (fp16 out)
        gemm_fp16_kernel<<<dim3(FF/BN, MB), 256, GEMM_SMEM>>>(
            ph, bwfc1 + (size_t)l*C*FF, f1b + (size_t)l*FF,
            nullptr, nullptr, 0, nullptr, pff, TOK, FF, C, 1, NTOK, 0, 0, 0);
        // x = x + g_mlp * (ff @ fc2_w + fc2_b)
        gemm_fp16_kernel<<<dim3(C/BN, MB), 256, GEMM_SMEM>>>(
            pff, bwfc2 + (size_t)l*FF*C, f2b + (size_t)l*C,
            px, pmodL + 5*C, 6*C, px, nullptr, TOK, C, FF, 2, NTOK, 0, 0, 0);
    }

    // fm = silu(c) @ final_w + final_b
    gemm_fp16_kernel<<<dim3(2*C/BN, 1), 256, GEMM_SMEM>>>(
        pcact, bwfin, fb, nullptr, nullptr, 0, pfm, nullptr, BATCH, 2*C, C, 0, NTOK, 0, 0, 0);
    // x = ln(x)*(1+f_scale)+f_shift
    ln_mod_kernel<<<TOK, 256>>>(px, nullptr, nullptr, pfm, C, 0, 2*C, ph);
    // logits = x @ head_w + head_b
    gemm_fp16_kernel<<<dim3(CBOOK/BN, MB), 256, GEMM_SMEM>>>(
        ph, bwhead, hb, nullptr, nullptr, 0, out, nullptr, TOK, CBOOK, C, 0, NTOK, 0, 0, 0);
}

// round 12
// speedup vs baseline: 1.0617x; 1.0617x over previous
#include <cuda_runtime.h>
#include <cuda_fp16.h>
#include <cstdint>
#include <math.h>

#define LNUM  12
#define C     1024
#define HN    16
#define HD    64
#define FF    4096
#define SEQ   256
#define BATCH 16
#define CBOOK 1024
#define NTOK  257
#define TOK   (BATCH*NTOK)   // 4112
#define EPS   1e-6f

typedef __half fp16;
struct __align__(8) H4 { __half2 a, b; };

// ---------------- scratch (device globals) -----------------------------------
__device__ float g_x[TOK*C];             // residual stream fp32
__device__ fp16  g_h[TOK*C];             // ln output (GEMM A)
__device__ float g_qkv[TOK*3*C];         // qkv fp32 (un-normalized; attn norms in-kernel)
__device__ fp16  g_o[TOK*C];             // attn out (GEMM A)
__device__ fp16  g_ff[TOK*FF];           // gelu out (GEMM A)
__device__ fp16  g_cact[BATCH*C];        // silu(c) (GEMM A)
__device__ float g_mod[LNUM*BATCH*6*C];  // per-layer modulation
__device__ float g_fm[BATCH*2*C];

// fp16 copies of all weights (converted every launch; deterministic)
__device__ fp16 w_qkv [LNUM*C*3*C];
__device__ fp16 w_proj[LNUM*C*C];
__device__ fp16 w_fc1 [LNUM*C*FF];
__device__ fp16 w_fc2 [LNUM*FF*C];
__device__ fp16 w_ada [LNUM*C*6*C];
__device__ fp16 w_fin [C*2*C];
__device__ fp16 w_head[C*CBOOK];

// ---------------- helpers ---------------------------------------------------
__device__ __forceinline__ float gelu_tanh(float x) {
    float x3 = x*x*x;
    float t  = tanhf(0.7978845608028654f*(x + 0.044715f*x3));
    return 0.5f*x*(1.0f + t);
}

__device__ __forceinline__ void cp_async16(uint32_t s, const void* g, bool p) {
    int sz = p ? 16 : 0;
    asm volatile("cp.async.cg.shared.global [%0], [%1], 16, %2;\n"
                 :: "r"(s), "l"(g), "r"(sz));
}
__device__ __forceinline__ void cp_commit() { asm volatile("cp.async.commit_group;\n"); }

__device__ __forceinline__ void ldm_x4(uint32_t &r0, uint32_t &r1, uint32_t &r2, uint32_t &r3, uint32_t a){
    asm volatile("ldmatrix.sync.aligned.m8n8.x4.shared.b16 {%0,%1,%2,%3},[%4];"
                 : "=r"(r0),"=r"(r1),"=r"(r2),"=r"(r3) : "r"(a));
}
__device__ __forceinline__ void ldm_x4_t(uint32_t &r0, uint32_t &r1, uint32_t &r2, uint32_t &r3, uint32_t a){
    asm volatile("ldmatrix.sync.aligned.m8n8.x4.trans.shared.b16 {%0,%1,%2,%3},[%4];"
                 : "=r"(r0),"=r"(r1),"=r"(r2),"=r"(r3) : "r"(a));
}
__device__ __forceinline__ void mma_fp16(float* c, const uint32_t* a, uint32_t b0, uint32_t b1){
    asm volatile("mma.sync.aligned.m16n8k16.row.col.f32.f16.f16.f32 "
                 "{%0,%1,%2,%3},{%4,%5,%6,%7},{%8,%9},{%0,%1,%2,%3};"
                 : "+f"(c[0]),"+f"(c[1]),"+f"(c[2]),"+f"(c[3])
                 : "r"(a[0]),"r"(a[1]),"r"(a[2]),"r"(a[3]),"r"(b0),"r"(b1));
}

// ---------------- fused fp32 -> fp16 conversion (one launch, 7 segments) ----
struct CvtDesc {
    const float* src[7];
    fp16*        dst[7];
    long long    off[8];
};
__global__ void cvt_all_kernel(CvtDesc d) {
    long long i = (long long)blockIdx.x*blockDim.x + threadIdx.x;
    if (i >= d.off[7]) return;
    int s = 0;
    #pragma unroll
    for (int k = 1; k < 7; k++) if (i >= d.off[k]) s = k;
    long long j = i - d.off[s];
    float4 v = ((const float4*)d.src[s])[j];
    H4 hv;
    hv.a = __floats2half2_rn(v.x, v.y);
    hv.b = __floats2half2_rn(v.z, v.w);
    ((H4*)d.dst[s])[j] = hv;
}

// ---------------- embedding + conditioning ----------------------------------
__global__ void embed_kernel(const int* __restrict__ ids, const int* __restrict__ cond,
                             const float* __restrict__ table, const float* __restrict__ pos,
                             float* __restrict__ x)
{
    int i = blockIdx.x*blockDim.x + threadIdx.x;
    if (i >= TOK*C) return;
    int r = i / C, c = i % C;
    int b = r / NTOK, n = r % NTOK;
    int id = (n == 0) ? (cond[b] + CBOOK + 1) : ids[b*SEQ + (n-1)];
    x[i] = table[(size_t)id*C + c] + pos[(size_t)n*C + c];
}

__global__ void cact_kernel(const int* __restrict__ cond, const float* __restrict__ table,
                            fp16* __restrict__ cact)
{
    int i = blockIdx.x*blockDim.x + threadIdx.x;
    if (i >= BATCH*C) return;
    int b = i / C, c = i % C;
    float v = table[(size_t)(cond[b] + CBOOK + 1)*C + c];
    cact[i] = __float2half(v / (1.0f + __expf(-v)));
}

// ---------------- LayerNorm + adaLN modulate (fp16 out, vectorized) ---------
__global__ void ln_mod_kernel(const float* __restrict__ x,
                              const float* __restrict__ s, const float* __restrict__ bb,
                              const float* __restrict__ mod, int shift_off, int scale_off,
                              int modStride, fp16* __restrict__ out)
{
    __shared__ float sh[16];
    int r = blockIdx.x;
    int t = threadIdx.x;
    const float4 xv = ((const float4*)(x + (size_t)r*C))[t];
    float sum = xv.x + xv.y + xv.z + xv.w;
    float sq  = xv.x*xv.x + xv.y*xv.y + xv.z*xv.z + xv.w*xv.w;
    int lane = t & 31, w = t >> 5;
    #pragma unroll
    for (int o = 16; o; o >>= 1) {
        sum += __shfl_xor_sync(0xffffffffu, sum, o);
        sq  += __shfl_xor_sync(0xffffffffu, sq,  o);
    }
    if (lane == 0) { sh[w] = sum; sh[8+w] = sq; }
    __syncthreads();
    if (t < 32) {
        float a  = (lane < 8) ? sh[lane]   : 0.f;
        float b2 = (lane < 8) ? sh[8+lane] : 0.f;
        #pragma unroll
        for (int o = 4; o; o >>= 1) {
            a  += __shfl_xor_sync(0xffffffffu, a,  o);
            b2 += __shfl_xor_sync(0xffffffffu, b2, o);
        }
        if (lane == 0) { sh[0] = a; sh[1] = b2; }
    }
    __syncthreads();
    float mu   = sh[0] * (1.0f/C);
    float var  = sh[1] * (1.0f/C) - mu*mu;
    float rstd = rsqrtf(var + EPS);
    int b = r / NTOK;
    const float* m = mod + (size_t)b*modStride;
    float4 msc = ((const float4*)(m + scale_off))[t];
    float4 msh = ((const float4*)(m + shift_off))[t];
    float y0 = (xv.x - mu)*rstd, y1 = (xv.y - mu)*rstd;
    float y2 = (xv.z - mu)*rstd, y3 = (xv.w - mu)*rstd;
    if (s) {
        float4 sv = ((const float4*)s)[t];
        float4 bv = ((const float4*)bb)[t];
        y0 = y0*sv.x + bv.x; y1 = y1*sv.y + bv.y;
        y2 = y2*sv.z + bv.z; y3 = y3*sv.w + bv.w;
    }
    y0 = y0*(1.0f + msc.x) + msh.x;
    y1 = y1*(1.0f + msc.y) + msh.y;
    y2 = y2*(1.0f + msc.z) + msh.z;
    y3 = y3*(1.0f + msc.w) + msh.w;
    H4 hv;
    hv.a = __floats2half2_rn(y0, y1);
    hv.b = __floats2half2_rn(y2, y3);
    ((H4*)(out + (size_t)r*C))[t] = hv;
}

// ---------------- causal attention + fused qk-norm (fp16 out) ----------------
#define KS2 68
#define ATTN_SMEM_FLOATS (2*NTOK*KS2 + 8*264 + 8*64)
__global__ void attn_kernel(const float* __restrict__ qkv,
                            const float* __restrict__ qns, const float* __restrict__ qnb,
                            const float* __restrict__ kns, const float* __restrict__ knb,
                            fp16* __restrict__ o)
{
    extern __shared__ float sm[];
    float* ksm = sm;                     // [NTOK][68]
    float* vsm = sm + NTOK*KS2;          // [NTOK][68]
    float* scb = vsm + NTOK*KS2;         // [8][264]
    float* qsm = scb + 8*264;            // [8][64]

    int bh = blockIdx.x;
    int b = bh / HN, h = bh % HN;
    int tid = threadIdx.x, lane = tid & 31, w = tid >> 5;

    // per-lane norm params (2 dims per lane: lane and lane+32)
    float qs0 = qns[lane], qs1 = qns[lane+32];
    float qb0 = qnb[lane], qb1 = qnb[lane+32];
    float ks0 = kns[lane], ks1 = kns[lane+32];
    float kb0 = knb[lane], kb1 = knb[lane+32];

    for (int i = tid; i < NTOK*HD; i += 256) {
        int n = i >> 6, d = i & 63;
        const float* row = qkv + (size_t)(b*NTOK + n)*3*C + h*HD;
        ksm[n*KS2 + d] = row[C   + d];
        vsm[n*KS2 + d] = row[2*C + d];
    }
    __syncthreads();

    // fused K layernorm: each warp normalizes rows w, w+8, ...
    for (int j = w; j < NTOK; j += 8) {
        float* kr = ksm + j*KS2;
        float v0 = kr[lane], v1 = kr[lane+32];
        float sum = v0 + v1;
        #pragma unroll
        for (int o2 = 16; o2; o2 >>= 1) sum += __shfl_xor_sync(0xffffffffu, sum, o2);
        float mu = sum * (1.0f/HD);
        float d0 = v0 - mu, d1 = v1 - mu;
        float sq = d0*d0 + d1*d1;
        #pragma unroll
        for (int o2 = 16; o2; o2 >>= 1) sq += __shfl_xor_sync(0xffffffffu, sq, o2);
        float rstd = rsqrtf(sq*(1.0f/HD) + EPS);
        kr[lane]    = d0*rstd*ks0 + kb0;
        kr[lane+32] = d1*rstd*ks1 + kb1;
    }
    __syncthreads();

    float* sc = scb + w*264;
    float* qb = qsm + w*64;
    for (int q = w; q < NTOK; q += 8) {
        const float* qrow = qkv + (size_t)(b*NTOK + q)*3*C + h*HD;
        // fused q layernorm
        float v0 = qrow[lane], v1 = qrow[lane+32];
        float sum = v0 + v1;
        #pragma unroll
        for (int o2 = 16; o2; o2 >>= 1) sum += __shfl_xor_sync(0xffffffffu, sum, o2);
        float mu = sum * (1.0f/HD);
        float d0 = v0 - mu, d1 = v1 - mu;
        float sq = d0*d0 + d1*d1;
        #pragma unroll
        for (int o2 = 16; o2; o2 >>= 1) sq += __shfl_xor_sync(0xffffffffu, sq, o2);
        float rstd = rsqrtf(sq*(1.0f/HD) + EPS);
        qb[lane]    = d0*rstd*qs0 + qb0;
        qb[lane+32] = d1*rstd*qs1 + qb1;
        __syncwarp();
        float4 q4[16];
        #pragma unroll
        for (int i = 0; i < 16; i++) q4[i] = ((const float4*)qb)[i];

        float mx = -1e30f;
        for (int j = lane; j <= q; j += 32) {
            const float4* kr = (const float4*)(ksm + j*KS2);
            float s = 0.f;
            #pragma unroll
            for (int i = 0; i < 16; i++) {
                float4 kv = kr[i];
                s += q4[i].x*kv.x + q4[i].y*kv.y + q4[i].z*kv.z + q4[i].w*kv.w;
            }
            s *= 0.125f;
            sc[j] = s;
            mx = fmaxf(mx, s);
        }
        #pragma unroll
        for (int off = 16; off; off >>= 1) mx = fmaxf(mx, __shfl_xor_sync(0xffffffffu, mx, off));
        __syncwarp();
        float Z = 0.f;
        for (int j = lane; j <= q; j += 32) {
            float p = __expf(sc[j] - mx);
            sc[j] = p; Z += p;
        }
        #pragma unroll
        for (int off = 16; off; off >>= 1) Z += __shfl_xor_sync(0xffffffffu, Z, off);
        __syncwarp();
        // PV: lane owns dims (2*lane, 2*lane+1)
        float o0 = 0.f, o1 = 0.f;
        const float* vbase = vsm + 2*lane;
        int j = 0;
        for (; j + 3 <= q; j += 4) {
            float p0 = sc[j], p1 = sc[j+1], p2 = sc[j+2], p3 = sc[j+3];
            float2 v0v = *(const float2*)(vbase + (j  )*KS2);
            float2 v1v = *(const float2*)(vbase + (j+1)*KS2);
            float2 v2v = *(const float2*)(vbase + (j+2)*KS2);
            float2 v3v = *(const float2*)(vbase + (j+3)*KS2);
            o0 += p0*v0v.x + p1*v1v.x + p2*v2v.x + p3*v3v.x;
            o1 += p0*v0v.y + p1*v1v.y + p2*v2v.y + p3*v3v.y;
        }
        for (; j <= q; j++) {
            float p = sc[j];
            float2 v0v = *(const float2*)(vbase + j*KS2);
            o0 += p*v0v.x;
            o1 += p*v0v.y;
        }
        float inv = 1.0f / Z;
        fp16* orow = o + (size_t)(b*NTOK + q)*C + h*HD;
        *(__half2*)(orow + 2*lane) = __floats2half2_rn(o0*inv, o1*inv);
        __syncwarp();
    }
}

// ---------------- fp16 tensor-core GEMM 128x128x32, 3-stage pipeline ---------
// (exact R10 configuration — the 7830us scheduling with regs=128)
// epi 0: Cf = acc + bias ; epi 1: Cb = gelu(acc+bias) fp16 ; epi 2: Cf = res + gate*(acc+bias)
// Optional z-batching: B/bias/Cf advance by zB/zBias/zC per blockIdx.z.
#define BM 128
#define BN 128
#define BK 32
#define ASTR 40
#define BSTR 136
#define STAGES 3
#define A_STAGE (BM*ASTR)
#define B_STAGE (BK*BSTR)
#define GEMM_SMEM ((STAGES*A_STAGE + STAGES*B_STAGE)*2)

__global__ __launch_bounds__(256) void gemm_fp16_kernel(
    const fp16* __restrict__ A, const fp16* __restrict__ B,
    const float* __restrict__ bias, const float* __restrict__ res,
    const float* __restrict__ gate, int gateStride,
    float* __restrict__ Cf, fp16* __restrict__ Cb,
    int M, int N, int K, int epi, int rowsPerBatch,
    size_t zB, size_t zC, int zBias)
{
    extern __shared__ __align__(16) fp16 smemh[];
    fp16* As = smemh;
    fp16* Bs = smemh + STAGES*A_STAGE;

    B    += (size_t)blockIdx.z * zB;
    bias += (size_t)blockIdx.z * zBias;
    Cf   += (size_t)blockIdx.z * zC;

    int tid = threadIdx.x;
    int warp = tid >> 5, lane = tid & 31;
    int wm = warp >> 1, wn = warp & 1;
    int m0 = blockIdx.y*BM, n0 = blockIdx.x*BN;

    float acc[2][8][4];
    #pragma unroll
    for (int i = 0; i < 2; i++)
        #pragma unroll
        for (int j = 0; j < 8; j++)
            #pragma unroll
            for (int k = 0; k < 4; k++) acc[i][j][k] = 0.f;

    int ar0 = tid >> 2;
    int ach = (tid & 3) << 3;
    int br0 = tid >> 4;
    int bch = (tid & 15) << 3;
    bool av0 = (m0 + ar0)      < M;
    bool av1 = (m0 + ar0 + 64) < M;

    int KT = K/BK;

    // prologue: stages 0..STAGES-2
    #pragma unroll
    for (int s = 0; s < STAGES-1; s++) {
        int k0 = s*BK;
        if (s < KT) {
            cp_async16((uint32_t)__cvta_generic_to_shared(&As[s*A_STAGE + ar0*ASTR + ach]),
                       A + (size_t)(m0+ar0)*K + k0 + ach, av0);
            cp_async16((uint32_t)__cvta_generic_to_shared(&As[s*A_STAGE + (ar0+64)*ASTR + ach]),
                       A + (size_t)(m0+ar0+64)*K + k0 + ach, av1);
            cp_async16((uint32_t)__cvta_generic_to_shared(&Bs[s*B_STAGE + br0*BSTR + bch]),
                       B + (size_t)(k0+br0)*N + n0 + bch, true);
            cp_async16((uint32_t)__cvta_generic_to_shared(&Bs[s*B_STAGE + (br0+16)*BSTR + bch]),
                       B + (size_t)(k0+br0+16)*N + n0 + bch, true);
        }
        cp_commit();
    }

    for (int kt = 0; kt < KT; kt++) {
        asm volatile("cp.async.wait_group %0;\n" :: "n"(STAGES-2));
        __syncthreads();

        int nk = kt + STAGES - 1;
        if (nk < KT) {
            int sl = nk % STAGES;
            int k0 = nk*BK;
            cp_async16((uint32_t)__cvta_generic_to_shared(&As[sl*A_STAGE + ar0*ASTR + ach]),
                       A + (size_t)(m0+ar0)*K + k0 + ach, av0);
            cp_async16((uint32_t)__cvta_generic_to_shared(&As[sl*A_STAGE + (ar0+64)*ASTR + ach]),
                       A + (size_t)(m0+ar0+64)*K + k0 + ach, av1);
            cp_async16((uint32_t)__cvta_generic_to_shared(&Bs[sl*B_STAGE + br0*BSTR + bch]),
                       B + (size_t)(k0+br0)*N + n0 + bch, true);
            cp_async16((uint32_t)__cvta_generic_to_shared(&Bs[sl*B_STAGE + (br0+16)*BSTR + bch]),
                       B + (size_t)(k0+br0+16)*N + n0 + bch, true);
        }
        cp_commit();

        const fp16* Ab = As + (kt % STAGES)*A_STAGE;
        const fp16* Bb = Bs + (kt % STAGES)*B_STAGE;
        #pragma unroll
        for (int ks = 0; ks < 2; ks++) {
            uint32_t a[2][4];
            #pragma unroll
            for (int mi = 0; mi < 2; mi++) {
                int row  = wm*32 + mi*16 + (lane & 15);
                int koff = ks*16 + ((lane >> 4) << 3);
                ldm_x4(a[mi][0], a[mi][1], a[mi][2], a[mi][3],
                       (uint32_t)__cvta_generic_to_shared(&Ab[row*ASTR + koff]));
            }
            #pragma unroll
            for (int ntp = 0; ntp < 4; ntp++) {
                int kr   = ks*16 + (lane & 7) + (((lane >> 3) & 1) << 3);
                int noff = wn*64 + ntp*16 + (((lane >> 4) & 1) << 3);
                uint32_t b0, b1, b2, b3;
                ldm_x4_t(b0, b1, b2, b3,
                         (uint32_t)__cvta_generic_to_shared(&Bb[kr*BSTR + noff]));
                #pragma unroll
                for (int mi = 0; mi < 2; mi++) {
                    mma_fp16(acc[mi][2*ntp],   a[mi], b0, b1);
                    mma_fp16(acc[mi][2*ntp+1], a[mi], b2, b3);
                }
            }
        }
    }

    // epilogue
    int rbase = m0 + wm*32 + (lane >> 2);
    int cbase = n0 + wn*64 + (lane & 3)*2;
    #pragma unroll
    for (int mi = 0; mi < 2; mi++) {
        #pragma unroll
        for (int hh = 0; hh < 2; hh++) {
            int row = rbase + mi*16 + hh*8;
            if (row >= M) continue;
            int bidx = row / rowsPerBatch;
            #pragma unroll
            for (int nt = 0; nt < 8; nt++) {
                int col = cbase + nt*8;
                float v0 = acc[mi][nt][2*hh]   + bias[col];
                float v1 = acc[mi][nt][2*hh+1] + bias[col+1];
                if (epi == 1) {
                    v0 = gelu_tanh(v0); v1 = gelu_tanh(v1);
                    *(__half2*)(Cb + (size_t)row*N + col) = __floats2half2_rn(v0, v1);
                } else if (epi == 2) {
                    const float* rr = res + (size_t)row*N + col;
                    const float* gg = gate + (size_t)bidx*gateStride + col;
                    v0 = rr[0] + gg[0]*v0;
                    v1 = rr[1] + gg[1]*v1;
                    *(float2*)(Cf + (size_t)row*N + col) = make_float2(v0, v1);
                } else {
                    *(float2*)(Cf + (size_t)row*N + col) = make_float2(v0, v1);
                }
            }
        }
    }
}

// ---------------- driver -----------------------------------------------------
extern "C" void kernel_launch(void* const* d_in, const int* in_sizes, int n_in,
                              void* d_out, int out_size)
{
    const int*   ids   = (const int*)  d_in[0];
    const int*   cond  = (const int*)  d_in[1];
    const float* table = (const float*)d_in[2];
    const float* pos   = (const float*)d_in[3];
    const float* n1s   = (const float*)d_in[4];
    const float* n1b   = (const float*)d_in[5];
    const float* qkvw  = (const float*)d_in[6];
    const float* qkvb  = (const float*)d_in[7];
    const float* qns   = (const float*)d_in[8];
    const float* qnb   = (const float*)d_in[9];
    const float* kns   = (const float*)d_in[10];
    const float* knb   = (const float*)d_in[11];
    const float* projw = (const float*)d_in[12];
    const float* projb = (const float*)d_in[13];
    const float* n2s   = (const float*)d_in[14];
    const float* n2b   = (const float*)d_in[15];
    const float* f1w   = (const float*)d_in[16];
    const float* f1b   = (const float*)d_in[17];
    const float* f2w   = (const float*)d_in[18];
    const float* f2b   = (const float*)d_in[19];
    const float* aw    = (const float*)d_in[20];
    const float* ab    = (const float*)d_in[21];
    const float* fw    = (const float*)d_in[22];
    const float* fb    = (const float*)d_in[23];
    const float* hw    = (const float*)d_in[24];
    const float* hb    = (const float*)d_in[25];
    float* out = (float*)d_out;

    void *vx, *vh, *vqkv, *vo, *vff, *vcact, *vmod, *vfm;
    void *vwqkv, *vwproj, *vwfc1, *vwfc2, *vwada, *vwfin, *vwhead;
    cudaGetSymbolAddress(&vx,    g_x);
    cudaGetSymbolAddress(&vh,    g_h);
    cudaGetSymbolAddress(&vqkv,  g_qkv);
    cudaGetSymbolAddress(&vo,    g_o);
    cudaGetSymbolAddress(&vff,   g_ff);
    cudaGetSymbolAddress(&vcact, g_cact);
    cudaGetSymbolAddress(&vmod,  g_mod);
    cudaGetSymbolAddress(&vfm,   g_fm);
    cudaGetSymbolAddress(&vwqkv, w_qkv);
    cudaGetSymbolAddress(&vwproj,w_proj);
    cudaGetSymbolAddress(&vwfc1, w_fc1);
    cudaGetSymbolAddress(&vwfc2, w_fc2);
    cudaGetSymbolAddress(&vwada, w_ada);
    cudaGetSymbolAddress(&vwfin, w_fin);
    cudaGetSymbolAddress(&vwhead,w_head);

    float* px    = (float*)vx;
    fp16*  ph    = (fp16*) vh;
    float* pqkv  = (float*)vqkv;
    fp16*  po    = (fp16*) vo;
    fp16*  pff   = (fp16*) vff;
    fp16*  pcact = (fp16*) vcact;
    float* pmod  = (float*)vmod;
    float* pfm   = (float*)vfm;
    fp16*  bwqkv = (fp16*) vwqkv;
    fp16*  bwproj= (fp16*) vwproj;
    fp16*  bwfc1 = (fp16*) vwfc1;
    fp16*  bwfc2 = (fp16*) vwfc2;
    fp16*  bwada = (fp16*) vwada;
    fp16*  bwfin = (fp16*) vwfin;
    fp16*  bwhead= (fp16*) vwhead;

    int attnSmem = ATTN_SMEM_FLOATS * (int)sizeof(float);
    cudaFuncSetAttribute(attn_kernel, cudaFuncAttributeMaxDynamicSharedMemorySize, attnSmem);
    cudaFuncSetAttribute(gemm_fp16_kernel, cudaFuncAttributeMaxDynamicSharedMemorySize, GEMM_SMEM);

    // single fused conversion launch
    CvtDesc cd;
    long long c0 = (long long)LNUM*C*3*C/4;
    long long c1 = (long long)LNUM*C*C/4;
    long long c2 = (long long)LNUM*C*FF/4;
    long long c3 = (long long)LNUM*FF*C/4;
    long long c4 = (long long)LNUM*C*6*C/4;
    long long c5 = (long long)C*2*C/4;
    long long c6 = (long long)C*CBOOK/4;
    cd.src[0]=qkvw;  cd.dst[0]=bwqkv;
    cd.src[1]=projw; cd.dst[1]=bwproj;
    cd.src[2]=f1w;   cd.dst[2]=bwfc1;
    cd.src[3]=f2w;   cd.dst[3]=bwfc2;
    cd.src[4]=aw;    cd.dst[4]=bwada;
    cd.src[5]=fw;    cd.dst[5]=bwfin;
    cd.src[6]=hw;    cd.dst[6]=bwhead;
    cd.off[0]=0;
    cd.off[1]=c0;
    cd.off[2]=c0+c1;
    cd.off[3]=c0+c1+c2;
    cd.off[4]=c0+c1+c2+c3;
    cd.off[5]=c0+c1+c2+c3+c4;
    cd.off[6]=c0+c1+c2+c3+c4+c5;
    cd.off[7]=c0+c1+c2+c3+c4+c5+c6;
    cvt_all_kernel<<<(unsigned)((cd.off[7] + 255)/256), 256>>>(cd);

    embed_kernel<<<(TOK*C + 255)/256, 256>>>(ids, cond, table, pos, px);
    cact_kernel<<<(BATCH*C + 255)/256, 256>>>(cond, table, pcact);

    // all layers' adaLN modulation in one batched GEMM: mod[l] = silu(c) @ aw[l] + ab[l]
    gemm_fp16_kernel<<<dim3(6*C/BN, 1, LNUM), 256, GEMM_SMEM>>>(
        pcact, bwada, ab, nullptr, nullptr, 0, pmod, nullptr,
        BATCH, 6*C, C, 0, NTOK,
        (size_t)C*6*C, (size_t)BATCH*6*C, 6*C);

    const int MB = (TOK + BM - 1) / BM;   // 33

    for (int l = 0; l < LNUM; l++) {
        float* pmodL = pmod + (size_t)l*BATCH*6*C;
        // h = ln1(x)*(1+sc_msa)+sh_msa
        ln_mod_kernel<<<TOK, 256>>>(px, n1s + (size_t)l*C, n1b + (size_t)l*C,
                                    pmodL, 0, C, 6*C, ph);
        // qkv = h @ qkv_w + qkv_b
        gemm_fp16_kernel<<<dim3(3*C/BN, MB), 256, GEMM_SMEM>>>(
            ph, bwqkv + (size_t)l*C*3*C, qkvb + (size_t)l*3*C,
            nullptr, nullptr, 0, pqkv, nullptr, TOK, 3*C, C, 0, NTOK, 0, 0, 0);
        // causal attention (fused qk layernorm)
        attn_kernel<<<BATCH*HN, 256, attnSmem>>>(pqkv,
            qns + (size_t)l*HD, qnb + (size_t)l*HD,
            kns + (size_t)l*HD, knb + (size_t)l*HD, po);
        // x = x + g_msa * (o @ proj_w + proj_b)
        gemm_fp16_kernel<<<dim3(C/BN, MB), 256, GEMM_SMEM>>>(
            po, bwproj + (size_t)l*C*C, projb + (size_t)l*C,
            px, pmodL + 2*C, 6*C, px, nullptr, TOK, C, C, 2, NTOK, 0, 0, 0);
        // h = ln2(x)*(1+sc_mlp)+sh_mlp
        ln_mod_kernel<<<TOK, 256>>>(px, n2s + (size_t)l*C, n2b + (size_t)l*C,
                                    pmodL, 3*C, 4*C, 6*C, ph);
        // ff = gelu(h @ fc1_w + fc1_b)  (fp16 out)
        gemm_fp16_kernel<<<dim3(FF/BN, MB), 256, GEMM_SMEM>>>(
            ph, bwfc1 + (size_t)l*C*FF, f1b + (size_t)l*FF,
            nullptr, nullptr, 0, nullptr, pff, TOK, FF, C, 1, NTOK, 0, 0, 0);
        // x = x + g_mlp * (ff @ fc2_w + fc2_b)
        gemm_fp16_kernel<<<dim3(C/BN, MB), 256, GEMM_SMEM>>>(
            pff, bwfc2 + (size_t)l*FF*C, f2b + (size_t)l*C,
            px, pmodL + 5*C, 6*C, px, nullptr, TOK, C, FF, 2, NTOK, 0, 0, 0);
    }

    // fm = silu(c) @ final_w + final_b
    gemm_fp16_kernel<<<dim3(2*C/BN, 1), 256, GEMM_SMEM>>>(
        pcact, bwfin, fb, nullptr, nullptr, 0, pfm, nullptr, BATCH, 2*C, C, 0, NTOK, 0, 0, 0);
    // x = ln(x)*(1+f_scale)+f_shift
    ln_mod_kernel<<<TOK, 256>>>(px, nullptr, nullptr, pfm, C, 0, 2*C, ph);
    // logits = x @ head_w + head_b
    gemm_fp16_kernel<<<dim3(CBOOK/BN, MB), 256, GEMM_SMEM>>>(
        ph, bwhead, hb, nullptr, nullptr, 0, out, nullptr, TOK, CBOOK, C, 0, NTOK, 0, 0, 0);
}

// round 14
// speedup vs baseline: 1.2296x; 1.1581x over previous
#include <cuda_runtime.h>
#include <cuda_fp16.h>
#include <cstdint>
#include <math.h>

#define LNUM  12
#define C     1024
#define HN    16
#define HD    64
#define FF    4096
#define SEQ   256
#define BATCH 16
#define CBOOK 1024
#define NTOK  257
#define TOK   (BATCH*NTOK)   // 4112
#define EPS   1e-6f

typedef __half fp16;
struct __align__(8) H4 { __half2 a, b; };

// ---------------- scratch (device globals) -----------------------------------
__device__ float g_x[TOK*C];             // residual stream fp32
__device__ fp16  g_h[TOK*C];             // ln output (GEMM A)
__device__ float g_qkv[TOK*3*C];         // qkv fp32 (qknorm normalizes in place)
__device__ fp16  g_o[TOK*C];             // attn out (GEMM A)
__device__ fp16  g_ff[TOK*FF];           // gelu out (GEMM A)
__device__ fp16  g_cact[BATCH*C];        // silu(c) (GEMM A)
__device__ float g_mod[LNUM*BATCH*6*C];  // per-layer modulation
__device__ float g_fm[BATCH*2*C];

// fp16 copies of all weights (converted every launch; deterministic)
__device__ fp16 w_qkv [LNUM*C*3*C];
__device__ fp16 w_proj[LNUM*C*C];
__device__ fp16 w_fc1 [LNUM*C*FF];
__device__ fp16 w_fc2 [LNUM*FF*C];
__device__ fp16 w_ada [LNUM*C*6*C];
__device__ fp16 w_fin [C*2*C];
__device__ fp16 w_head[C*CBOOK];

// ---------------- helpers ---------------------------------------------------
__device__ __forceinline__ float gelu_tanh(float x) {
    float x3 = x*x*x;
    float t  = tanhf(0.7978845608028654f*(x + 0.044715f*x3));
    return 0.5f*x*(1.0f + t);
}

__device__ __forceinline__ void cp_async16(uint32_t s, const void* g, bool p) {
    int sz = p ? 16 : 0;
    asm volatile("cp.async.cg.shared.global [%0], [%1], 16, %2;\n"
                 :: "r"(s), "l"(g), "r"(sz));
}
__device__ __forceinline__ void cp_commit() { asm volatile("cp.async.commit_group;\n"); }

__device__ __forceinline__ void ldm_x4(uint32_t &r0, uint32_t &r1, uint32_t &r2, uint32_t &r3, uint32_t a){
    asm volatile("ldmatrix.sync.aligned.m8n8.x4.shared.b16 {%0,%1,%2,%3},[%4];"
                 : "=r"(r0),"=r"(r1),"=r"(r2),"=r"(r3) : "r"(a));
}
__device__ __forceinline__ void ldm_x4_t(uint32_t &r0, uint32_t &r1, uint32_t &r2, uint32_t &r3, uint32_t a){
    asm volatile("ldmatrix.sync.aligned.m8n8.x4.trans.shared.b16 {%0,%1,%2,%3},[%4];"
                 : "=r"(r0),"=r"(r1),"=r"(r2),"=r"(r3) : "r"(a));
}
__device__ __forceinline__ void mma_fp16(float* c, const uint32_t* a, uint32_t b0, uint32_t b1){
    asm volatile("mma.sync.aligned.m16n8k16.row.col.f32.f16.f16.f32 "
                 "{%0,%1,%2,%3},{%4,%5,%6,%7},{%8,%9},{%0,%1,%2,%3};"
                 : "+f"(c[0]),"+f"(c[1]),"+f"(c[2]),"+f"(c[3])
                 : "r"(a[0]),"r"(a[1]),"r"(a[2]),"r"(a[3]),"r"(b0),"r"(b1));
}

// ---------------- fused fp32 -> fp16 conversion (one launch, 7 segments) ----
struct CvtDesc {
    const float* src[7];
    fp16*        dst[7];
    long long    off[8];
};
__global__ void cvt_all_kernel(CvtDesc d) {
    long long i = (long long)blockIdx.x*blockDim.x + threadIdx.x;
    if (i >= d.off[7]) return;
    int s = 0;
    #pragma unroll
    for (int k = 1; k < 7; k++) if (i >= d.off[k]) s = k;
    long long j = i - d.off[s];
    float4 v = ((const float4*)d.src[s])[j];
    H4 hv;
    hv.a = __floats2half2_rn(v.x, v.y);
    hv.b = __floats2half2_rn(v.z, v.w);
    ((H4*)d.dst[s])[j] = hv;
}

// ---------------- embedding + conditioning ----------------------------------
__global__ void embed_kernel(const int* __restrict__ ids, const int* __restrict__ cond,
                             const float* __restrict__ table, const float* __restrict__ pos,
                             float* __restrict__ x)
{
    int i = blockIdx.x*blockDim.x + threadIdx.x;
    if (i >= TOK*C) return;
    int r = i / C, c = i % C;
    int b = r / NTOK, n = r % NTOK;
    int id = (n == 0) ? (cond[b] + CBOOK + 1) : ids[b*SEQ + (n-1)];
    x[i] = table[(size_t)id*C + c] + pos[(size_t)n*C + c];
}

__global__ void cact_kernel(const int* __restrict__ cond, const float* __restrict__ table,
                            fp16* __restrict__ cact)
{
    int i = blockIdx.x*blockDim.x + threadIdx.x;
    if (i >= BATCH*C) return;
    int b = i / C, c = i % C;
    float v = table[(size_t)(cond[b] + CBOOK + 1)*C + c];
    cact[i] = __float2half(v / (1.0f + __expf(-v)));
}

// ---------------- LayerNorm + adaLN modulate (fp16 out, vectorized) ---------
__global__ void ln_mod_kernel(const float* __restrict__ x,
                              const float* __restrict__ s, const float* __restrict__ bb,
                              const float* __restrict__ mod, int shift_off, int scale_off,
                              int modStride, fp16* __restrict__ out)
{
    __shared__ float sh[16];
    int r = blockIdx.x;
    int t = threadIdx.x;
    const float4 xv = ((const float4*)(x + (size_t)r*C))[t];
    float sum = xv.x + xv.y + xv.z + xv.w;
    float sq  = xv.x*xv.x + xv.y*xv.y + xv.z*xv.z + xv.w*xv.w;
    int lane = t & 31, w = t >> 5;
    #pragma unroll
    for (int o = 16; o; o >>= 1) {
        sum += __shfl_xor_sync(0xffffffffu, sum, o);
        sq  += __shfl_xor_sync(0xffffffffu, sq,  o);
    }
    if (lane == 0) { sh[w] = sum; sh[8+w] = sq; }
    __syncthreads();
    if (t < 32) {
        float a  = (lane < 8) ? sh[lane]   : 0.f;
        float b2 = (lane < 8) ? sh[8+lane] : 0.f;
        #pragma unroll
        for (int o = 4; o; o >>= 1) {
            a  += __shfl_xor_sync(0xffffffffu, a,  o);
            b2 += __shfl_xor_sync(0xffffffffu, b2, o);
        }
        if (lane == 0) { sh[0] = a; sh[1] = b2; }
    }
    __syncthreads();
    float mu   = sh[0] * (1.0f/C);
    float var  = sh[1] * (1.0f/C) - mu*mu;
    float rstd = rsqrtf(var + EPS);
    int b = r / NTOK;
    const float* m = mod + (size_t)b*modStride;
    float4 msc = ((const float4*)(m + scale_off))[t];
    float4 msh = ((const float4*)(m + shift_off))[t];
    float y0 = (xv.x - mu)*rstd, y1 = (xv.y - mu)*rstd;
    float y2 = (xv.z - mu)*rstd, y3 = (xv.w - mu)*rstd;
    if (s) {
        float4 sv = ((const float4*)s)[t];
        float4 bv = ((const float4*)bb)[t];
        y0 = y0*sv.x + bv.x; y1 = y1*sv.y + bv.y;
        y2 = y2*sv.z + bv.z; y3 = y3*sv.w + bv.w;
    }
    y0 = y0*(1.0f + msc.x) + msh.x;
    y1 = y1*(1.0f + msc.y) + msh.y;
    y2 = y2*(1.0f + msc.z) + msh.z;
    y3 = y3*(1.0f + msc.w) + msh.w;
    H4 hv;
    hv.a = __floats2half2_rn(y0, y1);
    hv.b = __floats2half2_rn(y2, y3);
    ((H4*)(out + (size_t)r*C))[t] = hv;
}

// ---------------- per-head qk LayerNorm (separate kernel, as in R10) --------
__global__ void qknorm_kernel(float* __restrict__ qkv,
                              const float* __restrict__ qs, const float* __restrict__ qb,
                              const float* __restrict__ ks, const float* __restrict__ kb)
{
    int gw   = (blockIdx.x*blockDim.x + threadIdx.x) >> 5;
    int lane = threadIdx.x & 31;
    if (gw >= TOK*HN*2) return;
    int isK = (gw >= TOK*HN) ? 1 : 0;
    int rh  = isK ? gw - TOK*HN : gw;
    int r = rh / HN, h = rh % HN;
    float* p = qkv + (size_t)r*3*C + (isK ? C : 0) + h*HD;
    float v0 = p[lane], v1 = p[lane+32];
    float sum = v0 + v1;
    #pragma unroll
    for (int o = 16; o; o >>= 1) sum += __shfl_xor_sync(0xffffffffu, sum, o);
    float mu = sum * (1.0f/HD);
    float d0 = v0 - mu, d1 = v1 - mu;
    float sq = d0*d0 + d1*d1;
    #pragma unroll
    for (int o = 16; o; o >>= 1) sq += __shfl_xor_sync(0xffffffffu, sq, o);
    float rstd = rsqrtf(sq*(1.0f/HD) + EPS);
    const float* sa = isK ? ks : qs;
    const float* ba = isK ? kb : qb;
    p[lane]    = d0*rstd*sa[lane]    + ba[lane];
    p[lane+32] = d1*rstd*sa[lane+32] + ba[lane+32];
}

// ---------------- causal attention v3: fp16 K/V smem, HFMA2 scores -----------
// KSH = 72 halves (144 B row stride): multiple of 16 B (uint4-aligned for every
// row) and 36 words -> 8-lane LDS.128 phases hit banks {0,4,...,28}: conflict-free.
#define KSH 72
#define ATTN_SMEM_BYTES (2*NTOK*KSH*2 + 8*264*4 + 8*64*4)
__global__ void attn_kernel(const float* __restrict__ qkv, fp16* __restrict__ o)
{
    extern __shared__ __align__(16) char smraw[];
    __half* ksm = (__half*)smraw;                  // [NTOK][KSH]
    __half* vsm = ksm + NTOK*KSH;                  // [NTOK][KSH]
    float* scb = (float*)(vsm + NTOK*KSH);         // [8][264]
    float* qsm = scb + 8*264;                      // [8][64]

    int bh = blockIdx.x;
    int b = bh / HN, h = bh % HN;
    int tid = threadIdx.x, lane = tid & 31, w = tid >> 5;

    for (int i = tid; i < NTOK*HD; i += 256) {
        int n = i >> 6, d = i & 63;
        const float* row = qkv + (size_t)(b*NTOK + n)*3*C + h*HD;
        ksm[n*KSH + d] = __float2half(row[C   + d]);
        vsm[n*KSH + d] = __float2half(row[2*C + d]);
    }
    __syncthreads();

    float* sc = scb + w*264;
    float* qb = qsm + w*64;
    const __half2 h2zero = __float2half2_rn(0.f);
    for (int q = w; q < NTOK; q += 8) {
        const float* qrow = qkv + (size_t)(b*NTOK + q)*3*C + h*HD;
        qb[lane]    = qrow[lane];
        qb[lane+32] = qrow[lane+32];
        __syncwarp();
        // q as 32 half2 registers
        __half2 qh[32];
        #pragma unroll
        for (int i = 0; i < 16; i++) {
            float4 qv = ((const float4*)qb)[i];
            qh[2*i]   = __floats2half2_rn(qv.x, qv.y);
            qh[2*i+1] = __floats2half2_rn(qv.z, qv.w);
        }

        float mx = -1e30f;
        for (int j = lane; j <= q; j += 32) {
            const uint4* kr = (const uint4*)(ksm + j*KSH);
            __half2 a0 = h2zero, a1 = h2zero, a2 = h2zero, a3 = h2zero;
            #pragma unroll
            for (int i = 0; i < 8; i++) {
                uint4 kv = kr[i];
                a0 = __hfma2(qh[4*i+0], *(__half2*)&kv.x, a0);
                a1 = __hfma2(qh[4*i+1], *(__half2*)&kv.y, a1);
                a2 = __hfma2(qh[4*i+2], *(__half2*)&kv.z, a2);
                a3 = __hfma2(qh[4*i+3], *(__half2*)&kv.w, a3);
            }
            __half2 sh2 = __hadd2(__hadd2(a0, a1), __hadd2(a2, a3));
            float2 sf = __half22float2(sh2);
            float s = (sf.x + sf.y) * 0.125f;
            sc[j] = s;
            mx = fmaxf(mx, s);
        }
        #pragma unroll
        for (int off = 16; off; off >>= 1) mx = fmaxf(mx, __shfl_xor_sync(0xffffffffu, mx, off));
        __syncwarp();
        float Z = 0.f;
        for (int j = lane; j <= q; j += 32) {
            float p = __expf(sc[j] - mx);
            sc[j] = p; Z += p;
        }
        #pragma unroll
        for (int off = 16; off; off >>= 1) Z += __shfl_xor_sync(0xffffffffu, Z, off);
        __syncwarp();
        // PV: lane owns dims (2*lane, 2*lane+1); half2 loads, fp32 accumulate
        float o0 = 0.f, o1 = 0.f;
        int j = 0;
        for (; j + 3 <= q; j += 4) {
            float p0 = sc[j], p1 = sc[j+1], p2 = sc[j+2], p3 = sc[j+3];
            float2 v0 = __half22float2(*((const __half2*)(vsm + (j  )*KSH) + lane));
            float2 v1 = __half22float2(*((const __half2*)(vsm + (j+1)*KSH) + lane));
            float2 v2 = __half22float2(*((const __half2*)(vsm + (j+2)*KSH) + lane));
            float2 v3 = __half22float2(*((const __half2*)(vsm + (j+3)*KSH) + lane));
            o0 += p0*v0.x + p1*v1.x + p2*v2.x + p3*v3.x;
            o1 += p0*v0.y + p1*v1.y + p2*v2.y + p3*v3.y;
        }
        for (; j <= q; j++) {
            float p = sc[j];
            float2 v0 = __half22float2(*((const __half2*)(vsm + j*KSH) + lane));
            o0 += p*v0.x;
            o1 += p*v0.y;
        }
        float inv = 1.0f / Z;
        fp16* orow = o + (size_t)(b*NTOK + q)*C + h*HD;
        *(__half2*)(orow + 2*lane) = __floats2half2_rn(o0*inv, o1*inv);
        __syncwarp();
    }
}

// ---------------- fp16 tensor-core GEMM 128x128x32, 3-stage pipeline ---------
// (exact R10 configuration — regs=128 scheduling)
// epi 0: Cf = acc + bias ; epi 1: Cb = gelu(acc+bias) fp16 ; epi 2: Cf = res + gate*(acc+bias)
// Optional z-batching: B/bias/Cf advance by zB/zBias/zC per blockIdx.z.
#define BM 128
#define BN 128
#define BK 32
#define ASTR 40
#define BSTR 136
#define STAGES 3
#define A_STAGE (BM*ASTR)
#define B_STAGE (BK*BSTR)
#define GEMM_SMEM ((STAGES*A_STAGE + STAGES*B_STAGE)*2)

__global__ __launch_bounds__(256) void gemm_fp16_kernel(
    const fp16* __restrict__ A, const fp16* __restrict__ B,
    const float* __restrict__ bias, const float* __restrict__ res,
    const float* __restrict__ gate, int gateStride,
    float* __restrict__ Cf, fp16* __restrict__ Cb,
    int M, int N, int K, int epi, int rowsPerBatch,
    size_t zB, size_t zC, int zBias)
{
    extern __shared__ __align__(16) fp16 smemh[];
    fp16* As = smemh;
    fp16* Bs = smemh + STAGES*A_STAGE;

    B    += (size_t)blockIdx.z * zB;
    bias += (size_t)blockIdx.z * zBias;
    Cf   += (size_t)blockIdx.z * zC;

    int tid = threadIdx.x;
    int warp = tid >> 5, lane = tid & 31;
    int wm = warp >> 1, wn = warp & 1;
    int m0 = blockIdx.y*BM, n0 = blockIdx.x*BN;

    float acc[2][8][4];
    #pragma unroll
    for (int i = 0; i < 2; i++)
        #pragma unroll
        for (int j = 0; j < 8; j++)
            #pragma unroll
            for (int k = 0; k < 4; k++) acc[i][j][k] = 0.f;

    int ar0 = tid >> 2;
    int ach = (tid & 3) << 3;
    int br0 = tid >> 4;
    int bch = (tid & 15) << 3;
    bool av0 = (m0 + ar0)      < M;
    bool av1 = (m0 + ar0 + 64) < M;

    int KT = K/BK;

    // prologue: stages 0..STAGES-2
    #pragma unroll
    for (int s = 0; s < STAGES-1; s++) {
        int k0 = s*BK;
        if (s < KT) {
            cp_async16((uint32_t)__cvta_generic_to_shared(&As[s*A_STAGE + ar0*ASTR + ach]),
                       A + (size_t)(m0+ar0)*K + k0 + ach, av0);
            cp_async16((uint32_t)__cvta_generic_to_shared(&As[s*A_STAGE + (ar0+64)*ASTR + ach]),
                       A + (size_t)(m0+ar0+64)*K + k0 + ach, av1);
            cp_async16((uint32_t)__cvta_generic_to_shared(&Bs[s*B_STAGE + br0*BSTR + bch]),
                       B + (size_t)(k0+br0)*N + n0 + bch, true);
            cp_async16((uint32_t)__cvta_generic_to_shared(&Bs[s*B_STAGE + (br0+16)*BSTR + bch]),
                       B + (size_t)(k0+br0+16)*N + n0 + bch, true);
        }
        cp_commit();
    }

    for (int kt = 0; kt < KT; kt++) {
        asm volatile("cp.async.wait_group %0;\n" :: "n"(STAGES-2));
        __syncthreads();

        int nk = kt + STAGES - 1;
        if (nk < KT) {
            int sl = nk % STAGES;
            int k0 = nk*BK;
            cp_async16((uint32_t)__cvta_generic_to_shared(&As[sl*A_STAGE + ar0*ASTR + ach]),
                       A + (size_t)(m0+ar0)*K + k0 + ach, av0);
            cp_async16((uint32_t)__cvta_generic_to_shared(&As[sl*A_STAGE + (ar0+64)*ASTR + ach]),
                       A + (size_t)(m0+ar0+64)*K + k0 + ach, av1);
            cp_async16((uint32_t)__cvta_generic_to_shared(&Bs[sl*B_STAGE + br0*BSTR + bch]),
                       B + (size_t)(k0+br0)*N + n0 + bch, true);
            cp_async16((uint32_t)__cvta_generic_to_shared(&Bs[sl*B_STAGE + (br0+16)*BSTR + bch]),
                       B + (size_t)(k0+br0+16)*N + n0 + bch, true);
        }
        cp_commit();

        const fp16* Ab = As + (kt % STAGES)*A_STAGE;
        const fp16* Bb = Bs + (kt % STAGES)*B_STAGE;
        #pragma unroll
        for (int ks = 0; ks < 2; ks++) {
            uint32_t a[2][4];
            #pragma unroll
            for (int mi = 0; mi < 2; mi++) {
                int row  = wm*32 + mi*16 + (lane & 15);
                int koff = ks*16 + ((lane >> 4) << 3);
                ldm_x4(a[mi][0], a[mi][1], a[mi][2], a[mi][3],
                       (uint32_t)__cvta_generic_to_shared(&Ab[row*ASTR + koff]));
            }
            #pragma unroll
            for (int ntp = 0; ntp < 4; ntp++) {
                int kr   = ks*16 + (lane & 7) + (((lane >> 3) & 1) << 3);
                int noff = wn*64 + ntp*16 + (((lane >> 4) & 1) << 3);
                uint32_t b0, b1, b2, b3;
                ldm_x4_t(b0, b1, b2, b3,
                         (uint32_t)__cvta_generic_to_shared(&Bb[kr*BSTR + noff]));
                #pragma unroll
                for (int mi = 0; mi < 2; mi++) {
                    mma_fp16(acc[mi][2*ntp],   a[mi], b0, b1);
                    mma_fp16(acc[mi][2*ntp+1], a[mi], b2, b3);
                }
            }
        }
    }

    // epilogue
    int rbase = m0 + wm*32 + (lane >> 2);
    int cbase = n0 + wn*64 + (lane & 3)*2;
    #pragma unroll
    for (int mi = 0; mi < 2; mi++) {
        #pragma unroll
        for (int hh = 0; hh < 2; hh++) {
            int row = rbase + mi*16 + hh*8;
            if (row >= M) continue;
            int bidx = row / rowsPerBatch;
            #pragma unroll
            for (int nt = 0; nt < 8; nt++) {
                int col = cbase + nt*8;
                float v0 = acc[mi][nt][2*hh]   + bias[col];
                float v1 = acc[mi][nt][2*hh+1] + bias[col+1];
                if (epi == 1) {
                    v0 = gelu_tanh(v0); v1 = gelu_tanh(v1);
                    *(__half2*)(Cb + (size_t)row*N + col) = __floats2half2_rn(v0, v1);
                } else if (epi == 2) {
                    const float* rr = res + (size_t)row*N + col;
                    const float* gg = gate + (size_t)bidx*gateStride + col;
                    v0 = rr[0] + gg[0]*v0;
                    v1 = rr[1] + gg[1]*v1;
                    *(float2*)(Cf + (size_t)row*N + col) = make_float2(v0, v1);
                } else {
                    *(float2*)(Cf + (size_t)row*N + col) = make_float2(v0, v1);
                }
            }
        }
    }
}

// ---------------- driver -----------------------------------------------------
extern "C" void kernel_launch(void* const* d_in, const int* in_sizes, int n_in,
                              void* d_out, int out_size)
{
    const int*   ids   = (const int*)  d_in[0];
    const int*   cond  = (const int*)  d_in[1];
    const float* table = (const float*)d_in[2];
    const float* pos   = (const float*)d_in[3];
    const float* n1s   = (const float*)d_in[4];
    const float* n1b   = (const float*)d_in[5];
    const float* qkvw  = (const float*)d_in[6];
    const float* qkvb  = (const float*)d_in[7];
    const float* qns   = (const float*)d_in[8];
    const float* qnb   = (const float*)d_in[9];
    const float* kns   = (const float*)d_in[10];
    const float* knb   = (const float*)d_in[11];
    const float* projw = (const float*)d_in[12];
    const float* projb = (const float*)d_in[13];
    const float* n2s   = (const float*)d_in[14];
    const float* n2b   = (const float*)d_in[15];
    const float* f1w   = (const float*)d_in[16];
    const float* f1b   = (const float*)d_in[17];
    const float* f2w   = (const float*)d_in[18];
    const float* f2b   = (const float*)d_in[19];
    const float* aw    = (const float*)d_in[20];
    const float* ab    = (const float*)d_in[21];
    const float* fw    = (const float*)d_in[22];
    const float* fb    = (const float*)d_in[23];
    const float* hw    = (const float*)d_in[24];
    const float* hb    = (const float*)d_in[25];
    float* out = (float*)d_out;

    void *vx, *vh, *vqkv, *vo, *vff, *vcact, *vmod, *vfm;
    void *vwqkv, *vwproj, *vwfc1, *vwfc2, *vwada, *vwfin, *vwhead;
    cudaGetSymbolAddress(&vx,    g_x);
    cudaGetSymbolAddress(&vh,    g_h);
    cudaGetSymbolAddress(&vqkv,  g_qkv);
    cudaGetSymbolAddress(&vo,    g_o);
    cudaGetSymbolAddress(&vff,   g_ff);
    cudaGetSymbolAddress(&vcact, g_cact);
    cudaGetSymbolAddress(&vmod,  g_mod);
    cudaGetSymbolAddress(&vfm,   g_fm);
    cudaGetSymbolAddress(&vwqkv, w_qkv);
    cudaGetSymbolAddress(&vwproj,w_proj);
    cudaGetSymbolAddress(&vwfc1, w_fc1);
    cudaGetSymbolAddress(&vwfc2, w_fc2);
    cudaGetSymbolAddress(&vwada, w_ada);
    cudaGetSymbolAddress(&vwfin, w_fin);
    cudaGetSymbolAddress(&vwhead,w_head);

    float* px    = (float*)vx;
    fp16*  ph    = (fp16*) vh;
    float* pqkv  = (float*)vqkv;
    fp16*  po    = (fp16*) vo;
    fp16*  pff   = (fp16*) vff;
    fp16*  pcact = (fp16*) vcact;
    float* pmod  = (float*)vmod;
    float* pfm   = (float*)vfm;
    fp16*  bwqkv = (fp16*) vwqkv;
    fp16*  bwproj= (fp16*) vwproj;
    fp16*  bwfc1 = (fp16*) vwfc1;
    fp16*  bwfc2 = (fp16*) vwfc2;
    fp16*  bwada = (fp16*) vwada;
    fp16*  bwfin = (fp16*) vwfin;
    fp16*  bwhead= (fp16*) vwhead;

    int attnSmem = ATTN_SMEM_BYTES;
    cudaFuncSetAttribute(attn_kernel, cudaFuncAttributeMaxDynamicSharedMemorySize, attnSmem);
    cudaFuncSetAttribute(gemm_fp16_kernel, cudaFuncAttributeMaxDynamicSharedMemorySize, GEMM_SMEM);

    // single fused conversion launch
    CvtDesc cd;
    long long c0 = (long long)LNUM*C*3*C/4;
    long long c1 = (long long)LNUM*C*C/4;
    long long c2 = (long long)LNUM*C*FF/4;
    long long c3 = (long long)LNUM*FF*C/4;
    long long c4 = (long long)LNUM*C*6*C/4;
    long long c5 = (long long)C*2*C/4;
    long long c6 = (long long)C*CBOOK/4;
    cd.src[0]=qkvw;  cd.dst[0]=bwqkv;
    cd.src[1]=projw; cd.dst[1]=bwproj;
    cd.src[2]=f1w;   cd.dst[2]=bwfc1;
    cd.src[3]=f2w;   cd.dst[3]=bwfc2;
    cd.src[4]=aw;    cd.dst[4]=bwada;
    cd.src[5]=fw;    cd.dst[5]=bwfin;
    cd.src[6]=hw;    cd.dst[6]=bwhead;
    cd.off[0]=0;
    cd.off[1]=c0;
    cd.off[2]=c0+c1;
    cd.off[3]=c0+c1+c2;
    cd.off[4]=c0+c1+c2+c3;
    cd.off[5]=c0+c1+c2+c3+c4;
    cd.off[6]=c0+c1+c2+c3+c4+c5;
    cd.off[7]=c0+c1+c2+c3+c4+c5+c6;
    cvt_all_kernel<<<(unsigned)((cd.off[7] + 255)/256), 256>>>(cd);

    embed_kernel<<<(TOK*C + 255)/256, 256>>>(ids, cond, table, pos, px);
    cact_kernel<<<(BATCH*C + 255)/256, 256>>>(cond, table, pcact);

    // all layers' adaLN modulation in one batched GEMM: mod[l] = silu(c) @ aw[l] + ab[l]
    gemm_fp16_kernel<<<dim3(6*C/BN, 1, LNUM), 256, GEMM_SMEM>>>(
        pcact, bwada, ab, nullptr, nullptr, 0, pmod, nullptr,
        BATCH, 6*C, C, 0, NTOK,
        (size_t)C*6*C, (size_t)BATCH*6*C, 6*C);

    const int MB = (TOK + BM - 1) / BM;   // 33

    for (int l = 0; l < LNUM; l++) {
        float* pmodL = pmod + (size_t)l*BATCH*6*C;
        // h = ln1(x)*(1+sc_msa)+sh_msa
        ln_mod_kernel<<<TOK, 256>>>(px, n1s + (size_t)l*C, n1b + (size_t)l*C,
                                    pmodL, 0, C, 6*C, ph);
        // qkv = h @ qkv_w + qkv_b
        gemm_fp16_kernel<<<dim3(3*C/BN, MB), 256, GEMM_SMEM>>>(
            ph, bwqkv + (size_t)l*C*3*C, qkvb + (size_t)l*3*C,
            nullptr, nullptr, 0, pqkv, nullptr, TOK, 3*C, C, 0, NTOK, 0, 0, 0);
        // per-head q/k layernorm
        qknorm_kernel<<<(TOK*HN*2)/8, 256>>>(pqkv, qns + (size_t)l*HD, qnb + (size_t)l*HD,
                                             kns + (size_t)l*HD, knb + (size_t)l*HD);
        // causal attention (fp16 K/V smem)
        attn_kernel<<<BATCH*HN, 256, attnSmem>>>(pqkv, po);
        // x = x + g_msa * (o @ proj_w + proj_b)
        gemm_fp16_kernel<<<dim3(C/BN, MB), 256, GEMM_SMEM>>>(
            po, bwproj + (size_t)l*C*C, projb + (size_t)l*C,
            px, pmodL + 2*C, 6*C, px, nullptr, TOK, C, C, 2, NTOK, 0, 0, 0);
        // h = ln2(x)*(1+sc_mlp)+sh_mlp
        ln_mod_kernel<<<TOK, 256>>>(px, n2s + (size_t)l*C, n2b + (size_t)l*C,
                                    pmodL, 3*C, 4*C, 6*C, ph);
        // ff = gelu(h @ fc1_w + fc1_b)  (fp16 out)
        gemm_fp16_kernel<<<dim3(FF/BN, MB), 256, GEMM_SMEM>>>(
            ph, bwfc1 + (size_t)l*C*FF, f1b + (size_t)l*FF,
            nullptr, nullptr, 0, nullptr, pff, TOK, FF, C, 1, NTOK, 0, 0, 0);
        // x = x + g_mlp * (ff @ fc2_w + fc2_b)
        gemm_fp16_kernel<<<dim3(C/BN, MB), 256, GEMM_SMEM>>>(
            pff, bwfc2 + (size_t)l*FF*C, f2b + (size_t)l*C,
            px, pmodL + 5*C, 6*C, px, nullptr, TOK, C, FF, 2, NTOK, 0, 0, 0);
    }

    // fm = silu(c) @ final_w + final_b
    gemm_fp16_kernel<<<dim3(2*C/BN, 1), 256, GEMM_SMEM>>>(
        pcact, bwfin, fb, nullptr, nullptr, 0, pfm, nullptr, BATCH, 2*C, C, 0, NTOK, 0, 0, 0);
    // x = ln(x)*(1+f_scale)+f_shift
    ln_mod_kernel<<<TOK, 256>>>(px, nullptr, nullptr, pfm, C, 0, 2*C, ph);
    // logits = x @ head_w + head_b
    gemm_fp16_kernel<<<dim3(CBOOK/BN, MB), 256, GEMM_SMEM>>>(
        ph, bwhead, hb, nullptr, nullptr, 0, out, nullptr, TOK, CBOOK, C, 0, NTOK, 0, 0, 0);
}

// round 17
// speedup vs baseline: 1.2660x; 1.0296x over previous
#include <cuda_runtime.h>
#include <cuda_fp16.h>
#include <cstdint>
#include <math.h>

#define LNUM  12
#define C     1024
#define HN    16
#define HD    64
#define FF    4096
#define SEQ   256
#define BATCH 16
#define CBOOK 1024
#define NTOK  257
#define TOK   (BATCH*NTOK)   // 4112
#define EPS   1e-6f

typedef __half fp16;
struct __align__(8) H4 { __half2 a, b; };

// ---------------- scratch (device globals) -----------------------------------
__device__ float g_x[TOK*C];             // residual stream fp32
__device__ fp16  g_h[TOK*C];             // ln output (GEMM A)
__device__ float g_qkv[TOK*3*C];         // qkv fp32 (q/k already head-normed by GEMM epilogue)
__device__ fp16  g_o[TOK*C];             // attn out (GEMM A)
__device__ fp16  g_ff[TOK*FF];           // gelu out (GEMM A)
__device__ fp16  g_cact[BATCH*C];        // silu(c) (GEMM A)
__device__ float g_mod[LNUM*BATCH*6*C];  // per-layer modulation
__device__ float g_fm[BATCH*2*C];

// fp16 copies of all weights (converted every launch; deterministic)
__device__ fp16 w_qkv [LNUM*C*3*C];
__device__ fp16 w_proj[LNUM*C*C];
__device__ fp16 w_fc1 [LNUM*C*FF];
__device__ fp16 w_fc2 [LNUM*FF*C];
__device__ fp16 w_ada [LNUM*C*6*C];
__device__ fp16 w_fin [C*2*C];
__device__ fp16 w_head[C*CBOOK];

// ---------------- helpers ---------------------------------------------------
__device__ __forceinline__ float gelu_tanh(float x) {
    float x3 = x*x*x;
    float t  = tanhf(0.7978845608028654f*(x + 0.044715f*x3));
    return 0.5f*x*(1.0f + t);
}

__device__ __forceinline__ void cp_async16(uint32_t s, const void* g, bool p) {
    int sz = p ? 16 : 0;
    asm volatile("cp.async.cg.shared.global [%0], [%1], 16, %2;\n"
                 :: "r"(s), "l"(g), "r"(sz));
}
__device__ __forceinline__ void cp_commit() { asm volatile("cp.async.commit_group;\n"); }

__device__ __forceinline__ void ldm_x4(uint32_t &r0, uint32_t &r1, uint32_t &r2, uint32_t &r3, uint32_t a){
    asm volatile("ldmatrix.sync.aligned.m8n8.x4.shared.b16 {%0,%1,%2,%3},[%4];"
                 : "=r"(r0),"=r"(r1),"=r"(r2),"=r"(r3) : "r"(a));
}
__device__ __forceinline__ void ldm_x4_t(uint32_t &r0, uint32_t &r1, uint32_t &r2, uint32_t &r3, uint32_t a){
    asm volatile("ldmatrix.sync.aligned.m8n8.x4.trans.shared.b16 {%0,%1,%2,%3},[%4];"
                 : "=r"(r0),"=r"(r1),"=r"(r2),"=r"(r3) : "r"(a));
}
__device__ __forceinline__ void mma_fp16(float* c, const uint32_t* a, uint32_t b0, uint32_t b1){
    asm volatile("mma.sync.aligned.m16n8k16.row.col.f32.f16.f16.f32 "
                 "{%0,%1,%2,%3},{%4,%5,%6,%7},{%8,%9},{%0,%1,%2,%3};"
                 : "+f"(c[0]),"+f"(c[1]),"+f"(c[2]),"+f"(c[3])
                 : "r"(a[0]),"r"(a[1]),"r"(a[2]),"r"(a[3]),"r"(b0),"r"(b1));
}

// ---------------- fused fp32 -> fp16 conversion (one launch, 7 segments) ----
struct CvtDesc {
    const float* src[7];
    fp16*        dst[7];
    long long    off[8];
};
__global__ void cvt_all_kernel(CvtDesc d) {
    long long i = (long long)blockIdx.x*blockDim.x + threadIdx.x;
    if (i >= d.off[7]) return;
    int s = 0;
    #pragma unroll
    for (int k = 1; k < 7; k++) if (i >= d.off[k]) s = k;
    long long j = i - d.off[s];
    float4 v = ((const float4*)d.src[s])[j];
    H4 hv;
    hv.a = __floats2half2_rn(v.x, v.y);
    hv.b = __floats2half2_rn(v.z, v.w);
    ((H4*)d.dst[s])[j] = hv;
}

// ---------------- embedding + conditioning ----------------------------------
__global__ void embed_kernel(const int* __restrict__ ids, const int* __restrict__ cond,
                             const float* __restrict__ table, const float* __restrict__ pos,
                             float* __restrict__ x)
{
    int i = blockIdx.x*blockDim.x + threadIdx.x;
    if (i >= TOK*C) return;
    int r = i / C, c = i % C;
    int b = r / NTOK, n = r % NTOK;
    int id = (n == 0) ? (cond[b] + CBOOK + 1) : ids[b*SEQ + (n-1)];
    x[i] = table[(size_t)id*C + c] + pos[(size_t)n*C + c];
}

__global__ void cact_kernel(const int* __restrict__ cond, const float* __restrict__ table,
                            fp16* __restrict__ cact)
{
    int i = blockIdx.x*blockDim.x + threadIdx.x;
    if (i >= BATCH*C) return;
    int b = i / C, c = i % C;
    float v = table[(size_t)(cond[b] + CBOOK + 1)*C + c];
    cact[i] = __float2half(v / (1.0f + __expf(-v)));
}

// ---------------- LayerNorm + adaLN modulate (fp16 out, vectorized) ---------
__global__ void ln_mod_kernel(const float* __restrict__ x,
                              const float* __restrict__ s, const float* __restrict__ bb,
                              const float* __restrict__ mod, int shift_off, int scale_off,
                              int modStride, fp16* __restrict__ out)
{
    __shared__ float sh[16];
    int r = blockIdx.x;
    int t = threadIdx.x;
    const float4 xv = ((const float4*)(x + (size_t)r*C))[t];
    float sum = xv.x + xv.y + xv.z + xv.w;
    float sq  = xv.x*xv.x + xv.y*xv.y + xv.z*xv.z + xv.w*xv.w;
    int lane = t & 31, w = t >> 5;
    #pragma unroll
    for (int o = 16; o; o >>= 1) {
        sum += __shfl_xor_sync(0xffffffffu, sum, o);
        sq  += __shfl_xor_sync(0xffffffffu, sq,  o);
    }
    if (lane == 0) { sh[w] = sum; sh[8+w] = sq; }
    __syncthreads();
    if (t < 32) {
        float a  = (lane < 8) ? sh[lane]   : 0.f;
        float b2 = (lane < 8) ? sh[8+lane] : 0.f;
        #pragma unroll
        for (int o = 4; o; o >>= 1) {
            a  += __shfl_xor_sync(0xffffffffu, a,  o);
            b2 += __shfl_xor_sync(0xffffffffu, b2, o);
        }
        if (lane == 0) { sh[0] = a; sh[1] = b2; }
    }
    __syncthreads();
    float mu   = sh[0] * (1.0f/C);
    float var  = sh[1] * (1.0f/C) - mu*mu;
    float rstd = rsqrtf(var + EPS);
    int b = r / NTOK;
    const float* m = mod + (size_t)b*modStride;
    float4 msc = ((const float4*)(m + scale_off))[t];
    float4 msh = ((const float4*)(m + shift_off))[t];
    float y0 = (xv.x - mu)*rstd, y1 = (xv.y - mu)*rstd;
    float y2 = (xv.z - mu)*rstd, y3 = (xv.w - mu)*rstd;
    if (s) {
        float4 sv = ((const float4*)s)[t];
        float4 bv = ((const float4*)bb)[t];
        y0 = y0*sv.x + bv.x; y1 = y1*sv.y + bv.y;
        y2 = y2*sv.z + bv.z; y3 = y3*sv.w + bv.w;
    }
    y0 = y0*(1.0f + msc.x) + msh.x;
    y1 = y1*(1.0f + msc.y) + msh.y;
    y2 = y2*(1.0f + msc.z) + msh.z;
    y3 = y3*(1.0f + msc.w) + msh.w;
    H4 hv;
    hv.a = __floats2half2_rn(y0, y1);
    hv.b = __floats2half2_rn(y2, y3);
    ((H4*)(out + (size_t)r*C))[t] = hv;
}

// ---------------- causal attention v3: fp16 K/V smem, HFMA2 scores -----------
#define KSH 72
#define ATTN_SMEM_BYTES (2*NTOK*KSH*2 + 8*264*4 + 8*64*4)
__global__ void attn_kernel(const float* __restrict__ qkv, fp16* __restrict__ o)
{
    extern __shared__ __align__(16) char smraw[];
    __half* ksm = (__half*)smraw;                  // [NTOK][KSH]
    __half* vsm = ksm + NTOK*KSH;                  // [NTOK][KSH]
    float* scb = (float*)(vsm + NTOK*KSH);         // [8][264]
    float* qsm = scb + 8*264;                      // [8][64]

    int bh = blockIdx.x;
    int b = bh / HN, h = bh % HN;
    int tid = threadIdx.x, lane = tid & 31, w = tid >> 5;

    for (int i = tid; i < NTOK*HD; i += 256) {
        int n = i >> 6, d = i & 63;
        const float* row = qkv + (size_t)(b*NTOK + n)*3*C + h*HD;
        ksm[n*KSH + d] = __float2half(row[C   + d]);
        vsm[n*KSH + d] = __float2half(row[2*C + d]);
    }
    __syncthreads();

    float* sc = scb + w*264;
    float* qb = qsm + w*64;
    const __half2 h2zero = __float2half2_rn(0.f);
    for (int q = w; q < NTOK; q += 8) {
        const float* qrow = qkv + (size_t)(b*NTOK + q)*3*C + h*HD;
        qb[lane]    = qrow[lane];
        qb[lane+32] = qrow[lane+32];
        __syncwarp();
        __half2 qh[32];
        #pragma unroll
        for (int i = 0; i < 16; i++) {
            float4 qv = ((const float4*)qb)[i];
            qh[2*i]   = __floats2half2_rn(qv.x, qv.y);
            qh[2*i+1] = __floats2half2_rn(qv.z, qv.w);
        }

        float mx = -1e30f;
        for (int j = lane; j <= q; j += 32) {
            const uint4* kr = (const uint4*)(ksm + j*KSH);
            __half2 a0 = h2zero, a1 = h2zero, a2 = h2zero, a3 = h2zero;
            #pragma unroll
            for (int i = 0; i < 8; i++) {
                uint4 kv = kr[i];
                a0 = __hfma2(qh[4*i+0], *(__half2*)&kv.x, a0);
                a1 = __hfma2(qh[4*i+1], *(__half2*)&kv.y, a1);
                a2 = __hfma2(qh[4*i+2], *(__half2*)&kv.z, a2);
                a3 = __hfma2(qh[4*i+3], *(__half2*)&kv.w, a3);
            }
            __half2 sh2 = __hadd2(__hadd2(a0, a1), __hadd2(a2, a3));
            float2 sf = __half22float2(sh2);
            float s = (sf.x + sf.y) * 0.125f;
            sc[j] = s;
            mx = fmaxf(mx, s);
        }
        #pragma unroll
        for (int off = 16; off; off >>= 1) mx = fmaxf(mx, __shfl_xor_sync(0xffffffffu, mx, off));
        __syncwarp();
        float Z = 0.f;
        for (int j = lane; j <= q; j += 32) {
            float p = __expf(sc[j] - mx);
            sc[j] = p; Z += p;
        }
        #pragma unroll
        for (int off = 16; off; off >>= 1) Z += __shfl_xor_sync(0xffffffffu, Z, off);
        __syncwarp();
        float o0 = 0.f, o1 = 0.f;
        int j = 0;
        for (; j + 3 <= q; j += 4) {
            float p0 = sc[j], p1 = sc[j+1], p2 = sc[j+2], p3 = sc[j+3];
            float2 v0 = __half22float2(*((const __half2*)(vsm + (j  )*KSH) + lane));
            float2 v1 = __half22float2(*((const __half2*)(vsm + (j+1)*KSH) + lane));
            float2 v2 = __half22float2(*((const __half2*)(vsm + (j+2)*KSH) + lane));
            float2 v3 = __half22float2(*((const __half2*)(vsm + (j+3)*KSH) + lane));
            o0 += p0*v0.x + p1*v1.x + p2*v2.x + p3*v3.x;
            o1 += p0*v0.y + p1*v1.y + p2*v2.y + p3*v3.y;
        }
        for (; j <= q; j++) {
            float p = sc[j];
            float2 v0 = __half22float2(*((const __half2*)(vsm + j*KSH) + lane));
            o0 += p*v0.x;
            o1 += p*v0.y;
        }
        float inv = 1.0f / Z;
        fp16* orow = o + (size_t)(b*NTOK + q)*C + h*HD;
        *(__half2*)(orow + 2*lane) = __floats2half2_rn(o0*inv, o1*inv);
        __syncwarp();
    }
}

// ---------------- fp16 tensor-core GEMM 128x128x32, 3-stage pipeline ---------
// epi 0: Cf = acc + bias
// epi 1: Cb = gelu(acc+bias) fp16
// epi 2: Cf = res + gate[b,col]*(acc+bias)
// epi 3: Cf = qkv with fused per-head q/k layernorm (N=3C, heads 64-wide,
//        warp n-tile = exactly one head; row stats via shfl over the 4-lane group)
#define BM 128
#define BN 128
#define BK 32
#define ASTR 40
#define BSTR 136
#define STAGES 3
#define A_STAGE (BM*ASTR)
#define B_STAGE (BK*BSTR)
#define GEMM_SMEM ((STAGES*A_STAGE + STAGES*B_STAGE)*2)

__global__ __launch_bounds__(256, 2) void gemm_fp16_kernel(
    const fp16* __restrict__ A, const fp16* __restrict__ B,
    const float* __restrict__ bias, const float* __restrict__ res,
    const float* __restrict__ gate, int gateStride,
    float* __restrict__ Cf, fp16* __restrict__ Cb,
    int M, int N, int K, int epi, int rowsPerBatch,
    size_t zB, size_t zC, int zBias,
    const float* __restrict__ nks, const float* __restrict__ nkb)
{
    extern __shared__ __align__(16) fp16 smemh[];
    fp16* As = smemh;
    fp16* Bs = smemh + STAGES*A_STAGE;

    B    += (size_t)blockIdx.z * zB;
    bias += (size_t)blockIdx.z * zBias;
    Cf   += (size_t)blockIdx.z * zC;

    int tid = threadIdx.x;
    int warp = tid >> 5, lane = tid & 31;
    int wm = warp >> 1, wn = warp & 1;
    int m0 = blockIdx.y*BM, n0 = blockIdx.x*BN;

    float acc[2][8][4];
    #pragma unroll
    for (int i = 0; i < 2; i++)
        #pragma unroll
        for (int j = 0; j < 8; j++)
            #pragma unroll
            for (int k = 0; k < 4; k++) acc[i][j][k] = 0.f;

    int ar0 = tid >> 2;
    int ach = (tid & 3) << 3;
    int br0 = tid >> 4;
    int bch = (tid & 15) << 3;
    bool av0 = (m0 + ar0)      < M;
    bool av1 = (m0 + ar0 + 64) < M;

    int KT = K/BK;

    // prologue: stages 0..STAGES-2
    #pragma unroll
    for (int s = 0; s < STAGES-1; s++) {
        int k0 = s*BK;
        if (s < KT) {
            cp_async16((uint32_t)__cvta_generic_to_shared(&As[s*A_STAGE + ar0*ASTR + ach]),
                       A + (size_t)(m0+ar0)*K + k0 + ach, av0);
            cp_async16((uint32_t)__cvta_generic_to_shared(&As[s*A_STAGE + (ar0+64)*ASTR + ach]),
                       A + (size_t)(m0+ar0+64)*K + k0 + ach, av1);
            cp_async16((uint32_t)__cvta_generic_to_shared(&Bs[s*B_STAGE + br0*BSTR + bch]),
                       B + (size_t)(k0+br0)*N + n0 + bch, true);
            cp_async16((uint32_t)__cvta_generic_to_shared(&Bs[s*B_STAGE + (br0+16)*BSTR + bch]),
                       B + (size_t)(k0+br0+16)*N + n0 + bch, true);
        }
        cp_commit();
    }

    for (int kt = 0; kt < KT; kt++) {
        asm volatile("cp.async.wait_group %0;\n" :: "n"(STAGES-2));
        __syncthreads();

        int nk = kt + STAGES - 1;
        if (nk < KT) {
            int sl = nk % STAGES;
            int k0 = nk*BK;
            cp_async16((uint32_t)__cvta_generic_to_shared(&As[sl*A_STAGE + ar0*ASTR + ach]),
                       A + (size_t)(m0+ar0)*K + k0 + ach, av0);
            cp_async16((uint32_t)__cvta_generic_to_shared(&As[sl*A_STAGE + (ar0+64)*ASTR + ach]),
                       A + (size_t)(m0+ar0+64)*K + k0 + ach, av1);
            cp_async16((uint32_t)__cvta_generic_to_shared(&Bs[sl*B_STAGE + br0*BSTR + bch]),
                       B + (size_t)(k0+br0)*N + n0 + bch, true);
            cp_async16((uint32_t)__cvta_generic_to_shared(&Bs[sl*B_STAGE + (br0+16)*BSTR + bch]),
                       B + (size_t)(k0+br0+16)*N + n0 + bch, true);
        }
        cp_commit();

        const fp16* Ab = As + (kt % STAGES)*A_STAGE;
        const fp16* Bb = Bs + (kt % STAGES)*B_STAGE;
        #pragma unroll
        for (int ks = 0; ks < 2; ks++) {
            uint32_t a[2][4];
            #pragma unroll
            for (int mi = 0; mi < 2; mi++) {
                int row  = wm*32 + mi*16 + (lane & 15);
                int koff = ks*16 + ((lane >> 4) << 3);
                ldm_x4(a[mi][0], a[mi][1], a[mi][2], a[mi][3],
                       (uint32_t)__cvta_generic_to_shared(&Ab[row*ASTR + koff]));
            }
            #pragma unroll
            for (int ntp = 0; ntp < 4; ntp++) {
                int kr   = ks*16 + (lane & 7) + (((lane >> 3) & 1) << 3);
                int noff = wn*64 + ntp*16 + (((lane >> 4) & 1) << 3);
                uint32_t b0, b1, b2, b3;
                ldm_x4_t(b0, b1, b2, b3,
                         (uint32_t)__cvta_generic_to_shared(&Bb[kr*BSTR + noff]));
                #pragma unroll
                for (int mi = 0; mi < 2; mi++) {
                    mma_fp16(acc[mi][2*ntp],   a[mi], b0, b1);
                    mma_fp16(acc[mi][2*ntp+1], a[mi], b2, b3);
                }
            }
        }
    }

    // epilogue
    int rbase = m0 + wm*32 + (lane >> 2);
    int cbase = n0 + wn*64 + (lane & 3)*2;
    if (epi == 3) {
        // qkv with fused q/k head-norm. seg: 0=q,1=k,2=v (warp's 64 cols are
        // entirely inside one segment since segments are 1024-aligned).
        int seg = (n0 + wn*64) >> 10;
        #pragma unroll
        for (int mi = 0; mi < 2; mi++) {
            #pragma unroll
            for (int hh = 0; hh < 2; hh++) {
                int row = rbase + mi*16 + hh*8;
                float vv[16];
                float s1 = 0.f, s2 = 0.f;
                #pragma unroll
                for (int nt = 0; nt < 8; nt++) {
                    int col = cbase + nt*8;
                    float v0 = acc[mi][nt][2*hh]   + bias[col];
                    float v1 = acc[mi][nt][2*hh+1] + bias[col+1];
                    vv[2*nt] = v0; vv[2*nt+1] = v1;
                    s1 += v0 + v1;
                    s2 += v0*v0 + v1*v1;
                }
                if (seg < 2) {
                    s1 += __shfl_xor_sync(0xffffffffu, s1, 1);
                    s1 += __shfl_xor_sync(0xffffffffu, s1, 2);
                    s2 += __shfl_xor_sync(0xffffffffu, s2, 1);
                    s2 += __shfl_xor_sync(0xffffffffu, s2, 2);
                    float mu   = s1 * (1.0f/HD);
                    float var  = s2 * (1.0f/HD) - mu*mu;
                    float rstd = rsqrtf(var + EPS);
                    const float* ns = (seg == 0) ? res  : nks;   // scale
                    const float* nb = (seg == 0) ? gate : nkb;   // bias
                    #pragma unroll
                    for (int nt = 0; nt < 8; nt++) {
                        int col = cbase + nt*8;
                        int d = col & 63;
                        vv[2*nt]   = (vv[2*nt]   - mu)*rstd*ns[d]   + nb[d];
                        vv[2*nt+1] = (vv[2*nt+1] - mu)*rstd*ns[d+1] + nb[d+1];
                    }
                }
                if (row < M) {
                    #pragma unroll
                    for (int nt = 0; nt < 8; nt++) {
                        int col = cbase + nt*8;
                        *(float2*)(Cf + (size_t)row*N + col) = make_float2(vv[2*nt], vv[2*nt+1]);
                    }
                }
            }
        }
    } else {
        #pragma unroll
        for (int mi = 0; mi < 2; mi++) {
            #pragma unroll
            for (int hh = 0; hh < 2; hh++) {
                int row = rbase + mi*16 + hh*8;
                if (row >= M) continue;
                int bidx = row / rowsPerBatch;
                #pragma unroll
                for (int nt = 0; nt < 8; nt++) {
                    int col = cbase + nt*8;
                    float v0 = acc[mi][nt][2*hh]   + bias[col];
                    float v1 = acc[mi][nt][2*hh+1] + bias[col+1];
                    if (epi == 1) {
                        v0 = gelu_tanh(v0); v1 = gelu_tanh(v1);
                        *(__half2*)(Cb + (size_t)row*N + col) = __floats2half2_rn(v0, v1);
                    } else if (epi == 2) {
                        const float* rr = res + (size_t)row*N + col;
                        const float* gg = gate + (size_t)bidx*gateStride + col;
                        v0 = rr[0] + gg[0]*v0;
                        v1 = rr[1] + gg[1]*v1;
                        *(float2*)(Cf + (size_t)row*N + col) = make_float2(v0, v1);
                    } else {
                        *(float2*)(Cf + (size_t)row*N + col) = make_float2(v0, v1);
                    }
                }
            }
        }
    }
}

// ---------------- driver -----------------------------------------------------
extern "C" void kernel_launch(void* const* d_in, const int* in_sizes, int n_in,
                              void* d_out, int out_size)
{
    const int*   ids   = (const int*)  d_in[0];
    const int*   cond  = (const int*)  d_in[1];
    const float* table = (const float*)d_in[2];
    const float* pos   = (const float*)d_in[3];
    const float* n1s   = (const float*)d_in[4];
    const float* n1b   = (const float*)d_in[5];
    const float* qkvw  = (const float*)d_in[6];
    const float* qkvb  = (const float*)d_in[7];
    const float* qns   = (const float*)d_in[8];
    const float* qnb   = (const float*)d_in[9];
    const float* kns   = (const float*)d_in[10];
    const float* knb   = (const float*)d_in[11];
    const float* projw = (const float*)d_in[12];
    const float* projb = (const float*)d_in[13];
    const float* n2s   = (const float*)d_in[14];
    const float* n2b   = (const float*)d_in[15];
    const float* f1w   = (const float*)d_in[16];
    const float* f1b   = (const float*)d_in[17];
    const float* f2w   = (const float*)d_in[18];
    const float* f2b   = (const float*)d_in[19];
    const float* aw    = (const float*)d_in[20];
    const float* ab    = (const float*)d_in[21];
    const float* fw    = (const float*)d_in[22];
    const float* fb    = (const float*)d_in[23];
    const float* hw    = (const float*)d_in[24];
    const float* hb    = (const float*)d_in[25];
    float* out = (float*)d_out;

    void *vx, *vh, *vqkv, *vo, *vff, *vcact, *vmod, *vfm;
    void *vwqkv, *vwproj, *vwfc1, *vwfc2, *vwada, *vwfin, *vwhead;
    cudaGetSymbolAddress(&vx,    g_x);
    cudaGetSymbolAddress(&vh,    g_h);
    cudaGetSymbolAddress(&vqkv,  g_qkv);
    cudaGetSymbolAddress(&vo,    g_o);
    cudaGetSymbolAddress(&vff,   g_ff);
    cudaGetSymbolAddress(&vcact, g_cact);
    cudaGetSymbolAddress(&vmod,  g_mod);
    cudaGetSymbolAddress(&vfm,   g_fm);
    cudaGetSymbolAddress(&vwqkv, w_qkv);
    cudaGetSymbolAddress(&vwproj,w_proj);
    cudaGetSymbolAddress(&vwfc1, w_fc1);
    cudaGetSymbolAddress(&vwfc2, w_fc2);
    cudaGetSymbolAddress(&vwada, w_ada);
    cudaGetSymbolAddress(&vwfin, w_fin);
    cudaGetSymbolAddress(&vwhead,w_head);

    float* px    = (float*)vx;
    fp16*  ph    = (fp16*) vh;
    float* pqkv  = (float*)vqkv;
    fp16*  po    = (fp16*) vo;
    fp16*  pff   = (fp16*) vff;
    fp16*  pcact = (fp16*) vcact;
    float* pmod  = (float*)vmod;
    float* pfm   = (float*)vfm;
    fp16*  bwqkv = (fp16*) vwqkv;
    fp16*  bwproj= (fp16*) vwproj;
    fp16*  bwfc1 = (fp16*) vwfc1;
    fp16*  bwfc2 = (fp16*) vwfc2;
    fp16*  bwada = (fp16*) vwada;
    fp16*  bwfin = (fp16*) vwfin;
    fp16*  bwhead= (fp16*) vwhead;

    int attnSmem = ATTN_SMEM_BYTES;
    cudaFuncSetAttribute(attn_kernel, cudaFuncAttributeMaxDynamicSharedMemorySize, attnSmem);
    cudaFuncSetAttribute(gemm_fp16_kernel, cudaFuncAttributeMaxDynamicSharedMemorySize, GEMM_SMEM);

    // single fused conversion launch
    CvtDesc cd;
    long long c0 = (long long)LNUM*C*3*C/4;
    long long c1 = (long long)LNUM*C*C/4;
    long long c2 = (long long)LNUM*C*FF/4;
    long long c3 = (long long)LNUM*FF*C/4;
    long long c4 = (long long)LNUM*C*6*C/4;
    long long c5 = (long long)C*2*C/4;
    long long c6 = (long long)C*CBOOK/4;
    cd.src[0]=qkvw;  cd.dst[0]=bwqkv;
    cd.src[1]=projw; cd.dst[1]=bwproj;
    cd.src[2]=f1w;   cd.dst[2]=bwfc1;
    cd.src[3]=f2w;   cd.dst[3]=bwfc2;
    cd.src[4]=aw;    cd.dst[4]=bwada;
    cd.src[5]=fw;    cd.dst[5]=bwfin;
    cd.src[6]=hw;    cd.dst[6]=bwhead;
    cd.off[0]=0;
    cd.off[1]=c0;
    cd.off[2]=c0+c1;
    cd.off[3]=c0+c1+c2;
    cd.off[4]=c0+c1+c2+c3;
    cd.off[5]=c0+c1+c2+c3+c4;
    cd.off[6]=c0+c1+c2+c3+c4+c5;
    cd.off[7]=c0+c1+c2+c3+c4+c5+c6;
    cvt_all_kernel<<<(unsigned)((cd.off[7] + 255)/256), 256>>>(cd);

    embed_kernel<<<(TOK*C + 255)/256, 256>>>(ids, cond, table, pos, px);
    cact_kernel<<<(BATCH*C + 255)/256, 256>>>(cond, table, pcact);

    // all layers' adaLN modulation in one batched GEMM: mod[l] = silu(c) @ aw[l] + ab[l]
    gemm_fp16_kernel<<<dim3(6*C/BN, 1, LNUM), 256, GEMM_SMEM>>>(
        pcact, bwada, ab, nullptr, nullptr, 0, pmod, nullptr,
        BATCH, 6*C, C, 0, NTOK,
        (size_t)C*6*C, (size_t)BATCH*6*C, 6*C, nullptr, nullptr);

    const int MB = (TOK + BM - 1) / BM;   // 33

    for (int l = 0; l < LNUM; l++) {
        float* pmodL = pmod + (size_t)l*BATCH*6*C;
        // h = ln1(x)*(1+sc_msa)+sh_msa
        ln_mod_kernel<<<TOK, 256>>>(px, n1s + (size_t)l*C, n1b + (size_t)l*C,
                                    pmodL, 0, C, 6*C, ph);
        // qkv = h @ qkv_w + qkv_b, with fused per-head q/k layernorm (epi=3)
        gemm_fp16_kernel<<<dim3(3*C/BN, MB), 256, GEMM_SMEM>>>(
            ph, bwqkv + (size_t)l*C*3*C, qkvb + (size_t)l*3*C,
            qns + (size_t)l*HD, qnb + (size_t)l*HD, 0,
            pqkv, nullptr, TOK, 3*C, C, 3, NTOK, 0, 0, 0,
            kns + (size_t)l*HD, knb + (size_t)l*HD);
        // causal attention (fp16 K/V smem)
        attn_kernel<<<BATCH*HN, 256, attnSmem>>>(pqkv, po);
        // x = x + g_msa * (o @ proj_w + proj_b)
        gemm_fp16_kernel<<<dim3(C/BN, MB), 256, GEMM_SMEM>>>(
            po, bwproj + (size_t)l*C*C, projb + (size_t)l*C,
            px, pmodL + 2*C, 6*C, px, nullptr, TOK, C, C, 2, NTOK, 0, 0, 0,
            nullptr, nullptr);
        // h = ln2(x)*(1+sc_mlp)+sh_mlp
        ln_mod_kernel<<<TOK, 256>>>(px, n2s + (size_t)l*C, n2b + (size_t)l*C,
                                    pmodL, 3*C, 4*C, 6*C, ph);
        // ff = gelu(h @ fc1_w + fc1_b)  (fp16 out)
        gemm_fp16_kernel<<<dim3(FF/BN, MB), 256, GEMM_SMEM>>>(
            ph, bwfc1 + (size_t)l*C*FF, f1b + (size_t)l*FF,
            nullptr, nullptr, 0, nullptr, pff, TOK, FF, C, 1, NTOK, 0, 0, 0,
            nullptr, nullptr);
        // x = x + g_mlp * (ff @ fc2_w + fc2_b)
        gemm_fp16_kernel<<<dim3(C/BN, MB), 256, GEMM_SMEM>>>(
            pff, bwfc2 + (size_t)l*FF*C, f2b + (size_t)l*C,
            px, pmodL + 5*C, 6*C, px, nullptr, TOK, C, FF, 2, NTOK, 0, 0, 0,
            nullptr, nullptr);
    }

    // fm = silu(c) @ final_w + final_b
    gemm_fp16_kernel<<<dim3(2*C/BN, 1), 256, GEMM_SMEM>>>(
        pcact, bwfin, fb, nullptr, nullptr, 0, pfm, nullptr, BATCH, 2*C, C, 0, NTOK, 0, 0, 0,
        nullptr, nullptr);
    // x = ln(x)*(1+f_scale)+f_shift
    ln_mod_kernel<<<TOK, 256>>>(px, nullptr, nullptr, pfm, C, 0, 2*C, ph);
    // logits = x @ head_w + head_b
    gemm_fp16_kernel<<<dim3(CBOOK/BN, MB), 256, GEMM_SMEM>>>(
        ph, bwhead, hb, nullptr, nullptr, 0, out, nullptr, TOK, CBOOK, C, 0, NTOK, 0, 0, 0,
        nullptr, nullptr);
}